// round 7
// baseline (speedup 1.0000x reference)
#include <cuda_runtime.h>
#include <cuda_bf16.h>
#include <math.h>
#include <stdint.h>

// Problem constants
#define S_LEN 2048
#define BATCH 2
#define HID   2048
#define NP    16
#define HN    128
#define M_ROWS (S_LEN*BATCH)     // 4096
#define QKV_N  (3*HID)           // 6144
#define HEAD_ELEMS ((size_t)BATCH * NP * S_LEN * HN)   // 8388608

// ---------------------------------------------------------------------------
// Scratch (device globals; no runtime allocation allowed)
// ---------------------------------------------------------------------------
__device__ float g_qkv[(size_t)M_ROWS * QKV_N];                 // [4096][6144]
__device__ __nv_bfloat16 g_qh[HEAD_ELEMS], g_ql[HEAD_ELEMS];    // [b][n][s][d]
__device__ __nv_bfloat16 g_kh[HEAD_ELEMS], g_kl[HEAD_ELEMS];
__device__ __nv_bfloat16 g_vh[HEAD_ELEMS], g_vl[HEAD_ELEMS];
__device__ __nv_bfloat16 g_hh[(size_t)M_ROWS * HID], g_hl[(size_t)M_ROWS * HID];
__device__ __nv_bfloat16 g_wqh[(size_t)QKV_N * HID], g_wql[(size_t)QKV_N * HID];
__device__ __nv_bfloat16 g_wdh[(size_t)HID * HID],  g_wdl[(size_t)HID * HID];
__device__ __nv_bfloat16 g_ch[(size_t)M_ROWS * HID], g_cl[(size_t)M_ROWS * HID];

// ---------------------------------------------------------------------------
// PTX helpers
// ---------------------------------------------------------------------------
__device__ __forceinline__ uint32_t smem_u32(const void* p) {
    return (uint32_t)__cvta_generic_to_shared(p);
}
__device__ __forceinline__ void ldsm_x4(uint32_t& r0, uint32_t& r1,
                                        uint32_t& r2, uint32_t& r3, uint32_t addr) {
    asm volatile("ldmatrix.sync.aligned.m8n8.x4.shared.b16 {%0,%1,%2,%3}, [%4];"
        : "=r"(r0), "=r"(r1), "=r"(r2), "=r"(r3) : "r"(addr));
}
__device__ __forceinline__ void ldsm_x4_t(uint32_t& r0, uint32_t& r1,
                                          uint32_t& r2, uint32_t& r3, uint32_t addr) {
    asm volatile("ldmatrix.sync.aligned.m8n8.x4.trans.shared.b16 {%0,%1,%2,%3}, [%4];"
        : "=r"(r0), "=r"(r1), "=r"(r2), "=r"(r3) : "r"(addr));
}
__device__ __forceinline__ void mma_bf16(float* d, const uint32_t* a, const uint32_t* b) {
    asm volatile("mma.sync.aligned.m16n8k16.row.col.f32.bf16.bf16.f32 "
        "{%0,%1,%2,%3}, {%4,%5,%6,%7}, {%8,%9}, {%0,%1,%2,%3};"
        : "+f"(d[0]), "+f"(d[1]), "+f"(d[2]), "+f"(d[3])
        : "r"(a[0]), "r"(a[1]), "r"(a[2]), "r"(a[3]), "r"(b[0]), "r"(b[1]));
}
__device__ __forceinline__ uint32_t pack_bf2(float a, float b) {
    __nv_bfloat162 t;
    t.x = __float2bfloat16_rn(a);
    t.y = __float2bfloat16_rn(b);
    return *(uint32_t*)&t;
}
__device__ __forceinline__ void cp16(void* sdst, const void* gsrc) {
    asm volatile("cp.async.cg.shared.global [%0], [%1], 16;\n"
        :: "r"(smem_u32(sdst)), "l"(gsrc));
}
__device__ __forceinline__ void cp_commit() {
    asm volatile("cp.async.commit_group;\n");
}
template <int N>
__device__ __forceinline__ void cp_wait() {
    asm volatile("cp.async.wait_group %0;\n" :: "n"(N));
}

// ---------------------------------------------------------------------------
// fp32 -> bf16 hi/lo split (element count multiple of 1024)
// ---------------------------------------------------------------------------
__global__ __launch_bounds__(256) void split_f32_bf16x2(
    const float* __restrict__ src,
    __nv_bfloat16* __restrict__ hi, __nv_bfloat16* __restrict__ lo)
{
    size_t i = ((size_t)blockIdx.x * 256 + threadIdx.x) * 4;
    float4 v = *(const float4*)(src + i);
    __nv_bfloat16 h0 = __float2bfloat16_rn(v.x);
    __nv_bfloat16 h1 = __float2bfloat16_rn(v.y);
    __nv_bfloat16 h2 = __float2bfloat16_rn(v.z);
    __nv_bfloat16 h3 = __float2bfloat16_rn(v.w);
    __nv_bfloat162 t;
    t.x = h0; t.y = h1; *(__nv_bfloat162*)(hi + i)     = t;
    t.x = h2; t.y = h3; *(__nv_bfloat162*)(hi + i + 2) = t;
    t.x = __float2bfloat16_rn(v.x - __bfloat162float(h0));
    t.y = __float2bfloat16_rn(v.y - __bfloat162float(h1));
    *(__nv_bfloat162*)(lo + i) = t;
    t.x = __float2bfloat16_rn(v.z - __bfloat162float(h2));
    t.y = __float2bfloat16_rn(v.w - __bfloat162float(h3));
    *(__nv_bfloat162*)(lo + i + 2) = t;
}

// ---------------------------------------------------------------------------
// Pure-bf16x3 GEMM (NT), pre-split operands, 3-stage cp.async pipeline.
// C[M,N] = (Ah+Al)[M,K] * (Bh+Bl)[N,K]^T + bias  (Ah*Bh + Ah*Bl + Al*Bh)
// BM=BN=128, BK=32, 256 threads (8 warps 4x2), warp tile 32x64.
// ---------------------------------------------------------------------------
#define TBM 128
#define TBN 128
#define TBK 32
#define TSTR 40
#define NSTAGE 3
#define PLANE (TBM*TSTR)                    // 5120 bf16
#define BOFF  (NSTAGE*2*PLANE)              // B matrix offset in smem
#define GEMM_SMEM_BYTES (NSTAGE*2*PLANE*2*2)  // 122880 B

__global__ __launch_bounds__(256, 1) void bf16x3_gemm_nt_bias(
    const __nv_bfloat16* __restrict__ Ah, const __nv_bfloat16* __restrict__ Al,
    const __nv_bfloat16* __restrict__ Bh, const __nv_bfloat16* __restrict__ Bl,
    const float* __restrict__ bias, float* __restrict__ C,
    int M, int N, int K)
{
    extern __shared__ __nv_bfloat16 smg[];

    const int tid  = threadIdx.x;
    const int bx   = blockIdx.x, by = blockIdx.y;
    const int warp = tid >> 5, lane = tid & 31;
    const int wr   = warp & 3;
    const int wc   = warp >> 2;

    // load mapping: 512 16B-chunks per plane; 2 chunks/thread/plane
    const int r0c = tid >> 2;          // base row (chunk 0)
    const int c0c = (tid & 3) * 8;     // bf16 col

    auto prefetch = [&](int kt, int s) {
        const size_t kof = (size_t)kt * TBK;
#pragma unroll
        for (int j = 0; j < 2; j++) {
            int r = r0c + j * 64;
            int so = r * TSTR + c0c;
            size_t ga = (size_t)(by * TBM + r) * K + kof + c0c;
            size_t gb = (size_t)(bx * TBN + r) * K + kof + c0c;
            cp16(smg + (size_t)(s * 2 + 0) * PLANE + so, Ah + ga);
            cp16(smg + (size_t)(s * 2 + 1) * PLANE + so, Al + ga);
            cp16(smg + BOFF + (size_t)(s * 2 + 0) * PLANE + so, Bh + gb);
            cp16(smg + BOFF + (size_t)(s * 2 + 1) * PLANE + so, Bl + gb);
        }
    };

    float acc[2][8][4];
#pragma unroll
    for (int mi = 0; mi < 2; mi++)
#pragma unroll
        for (int ni = 0; ni < 8; ni++)
#pragma unroll
            for (int e = 0; e < 4; e++) acc[mi][ni][e] = 0.f;

    // ldmatrix lane addressing
    const int a_row = wr * 32 + (lane & 15);
    const int a_kh  = (lane >> 4) * 8;
    const int bg    = lane >> 3;
    const int b_row = wc * 64 + ((bg >> 1) << 3) + (lane & 7);
    const int b_kh  = (bg & 1) * 8;

    auto compute = [&](int s) {
        const __nv_bfloat16* A0 = smg + (size_t)(s * 2 + 0) * PLANE;
        const __nv_bfloat16* A1 = smg + (size_t)(s * 2 + 1) * PLANE;
        const __nv_bfloat16* B0 = smg + BOFF + (size_t)(s * 2 + 0) * PLANE;
        const __nv_bfloat16* B1 = smg + BOFF + (size_t)(s * 2 + 1) * PLANE;
#pragma unroll
        for (int kk = 0; kk < TBK; kk += 16) {
            uint32_t af[2][2][4];
#pragma unroll
            for (int mi = 0; mi < 2; mi++) {
                ldsm_x4(af[0][mi][0], af[0][mi][1], af[0][mi][2], af[0][mi][3],
                        smem_u32(A0 + (a_row + mi * 16) * TSTR + kk + a_kh));
                ldsm_x4(af[1][mi][0], af[1][mi][1], af[1][mi][2], af[1][mi][3],
                        smem_u32(A1 + (a_row + mi * 16) * TSTR + kk + a_kh));
            }
            uint32_t bf[2][8][2];
#pragma unroll
            for (int np = 0; np < 4; np++) {
                uint32_t r0, r1, r2, r3;
                ldsm_x4(r0, r1, r2, r3,
                        smem_u32(B0 + (b_row + np * 16) * TSTR + kk + b_kh));
                bf[0][np * 2][0] = r0;     bf[0][np * 2][1] = r1;
                bf[0][np * 2 + 1][0] = r2; bf[0][np * 2 + 1][1] = r3;
                ldsm_x4(r0, r1, r2, r3,
                        smem_u32(B1 + (b_row + np * 16) * TSTR + kk + b_kh));
                bf[1][np * 2][0] = r0;     bf[1][np * 2][1] = r1;
                bf[1][np * 2 + 1][0] = r2; bf[1][np * 2 + 1][1] = r3;
            }
#pragma unroll
            for (int mi = 0; mi < 2; mi++)
#pragma unroll
                for (int ni = 0; ni < 8; ni++) {
                    mma_bf16(acc[mi][ni], af[0][mi], bf[0][ni]);   // Ah*Bh
                    mma_bf16(acc[mi][ni], af[0][mi], bf[1][ni]);   // Ah*Bl
                    mma_bf16(acc[mi][ni], af[1][mi], bf[0][ni]);   // Al*Bh
                }
        }
    };

    const int nt = K / TBK;
    prefetch(0, 0); cp_commit();
    prefetch(1, 1); cp_commit();
#pragma unroll 1
    for (int kt = 0; kt < nt; kt++) {
        cp_wait<1>();
        __syncthreads();
        if (kt + 2 < nt) prefetch(kt + 2, (kt + 2) % NSTAGE);
        cp_commit();
        compute(kt % NSTAGE);
    }

    // epilogue
    const int gr = lane >> 2, gc = (lane & 3) * 2;
#pragma unroll
    for (int mi = 0; mi < 2; mi++) {
        int row = by * TBM + wr * 32 + mi * 16 + gr;
#pragma unroll
        for (int ni = 0; ni < 8; ni++) {
            int col = bx * TBN + wc * 64 + ni * 8 + gc;
            float b0 = bias[col], b1 = bias[col + 1];
            float2 v0, v1;
            v0.x = acc[mi][ni][0] + b0; v0.y = acc[mi][ni][1] + b1;
            v1.x = acc[mi][ni][2] + b0; v1.y = acc[mi][ni][3] + b1;
            *(float2*)&C[(size_t)row * N + col] = v0;
            *(float2*)&C[(size_t)(row + 8) * N + col] = v1;
        }
    }
}

// ---------------------------------------------------------------------------
// Rotary + QKV split/transpose + bf16 hi/lo split.
// ---------------------------------------------------------------------------
__global__ __launch_bounds__(256) void rotary_split_kernel(
    const float* __restrict__ mixed,
    __nv_bfloat16* __restrict__ Qh, __nv_bfloat16* __restrict__ Ql,
    __nv_bfloat16* __restrict__ Kh, __nv_bfloat16* __restrict__ Kl,
    __nv_bfloat16* __restrict__ Vh, __nv_bfloat16* __restrict__ Vl)
{
    int idx = blockIdx.x * blockDim.x + threadIdx.x;
    int i = idx & 63;
    int rest = idx >> 6;
    int n = rest & (NP - 1); rest >>= 4;
    int b = rest & (BATCH - 1);
    int s = rest >> 1;

    const float* src = mixed + (((size_t)(s * BATCH + b)) * NP + n) * (3 * HN);
    size_t dst = (((size_t)b * NP + n) * S_LEN + s) * HN;

    float expo = (float)(2 * i) / (float)HN;
    float freq = powf(1e-4f, expo);
    float ang  = (float)s * freq;
    float sn, cs;
    sincosf(ang, &sn, &cs);

    const float qscale = 0.0883883476483184f;     // 1/sqrt(128)

    float ql_ = src[i],       qr_ = src[i + 64];
    float kl_ = src[128 + i], kr_ = src[192 + i];

    float q0 = (cs * ql_ - sn * qr_) * qscale;
    float q1 = (sn * ql_ + cs * qr_) * qscale;
    float k0 = cs * kl_ - sn * kr_;
    float k1 = sn * kl_ + cs * kr_;
    float v0 = src[256 + i];
    float v1 = src[320 + i];

    __nv_bfloat16 h;
    h = __float2bfloat16_rn(q0); Qh[dst + i] = h;
    Ql[dst + i] = __float2bfloat16_rn(q0 - __bfloat162float(h));
    h = __float2bfloat16_rn(q1); Qh[dst + 64 + i] = h;
    Ql[dst + 64 + i] = __float2bfloat16_rn(q1 - __bfloat162float(h));
    h = __float2bfloat16_rn(k0); Kh[dst + i] = h;
    Kl[dst + i] = __float2bfloat16_rn(k0 - __bfloat162float(h));
    h = __float2bfloat16_rn(k1); Kh[dst + 64 + i] = h;
    Kl[dst + 64 + i] = __float2bfloat16_rn(k1 - __bfloat162float(h));
    h = __float2bfloat16_rn(v0); Vh[dst + i] = h;
    Vl[dst + i] = __float2bfloat16_rn(v0 - __bfloat162float(h));
    h = __float2bfloat16_rn(v1); Vh[dst + 64 + i] = h;
    Vl[dst + 64 + i] = __float2bfloat16_rn(v1 - __bfloat162float(h));
}

// ---------------------------------------------------------------------------
// HMMA flash attention (bf16x3), cp.async double-buffered; ctx out as hi/lo.
// ---------------------------------------------------------------------------
#define FBM 128
#define FBN 64
#define FSTR 136
#define FA_STAGE_ELEMS (4*FBN*FSTR)
#define FA_SMEM_BYTES ((2*FBM*FSTR + 2*FA_STAGE_ELEMS) * 2)   // 208896

__global__ __launch_bounds__(256, 1) void flash_hmma_kernel(
    const __nv_bfloat16* __restrict__ Qhg, const __nv_bfloat16* __restrict__ Qlg,
    const __nv_bfloat16* __restrict__ Khg, const __nv_bfloat16* __restrict__ Klg,
    const __nv_bfloat16* __restrict__ Vhg, const __nv_bfloat16* __restrict__ Vlg,
    __nv_bfloat16* __restrict__ Ch, __nv_bfloat16* __restrict__ Cl)
{
    extern __shared__ __nv_bfloat16 fsm[];
    __nv_bfloat16* Qh = fsm;
    __nv_bfloat16* Ql = Qh + FBM * FSTR;
    __nv_bfloat16* St = Ql + FBM * FSTR;   // two stages of [Kh|Kl|Vh|Vl]

    const int qt = gridDim.x - 1 - blockIdx.x;    // heavy tiles first
    const int n  = blockIdx.y;
    const int b  = blockIdx.z;
    const int tid  = threadIdx.x;
    const int warp = tid >> 5, lane = tid & 31;

    const size_t head = ((size_t)b * NP + n) * (size_t)S_LEN * HN;
    const int row0 = qt * FBM;

    auto prefetch = [&](int kt, int s) {
        __nv_bfloat16* Khs = St + (size_t)s * FA_STAGE_ELEMS;
        __nv_bfloat16* Kls = Khs + FBN * FSTR;
        __nv_bfloat16* Vhs = Kls + FBN * FSTR;
        __nv_bfloat16* Vls = Vhs + FBN * FSTR;
        size_t base = head + (size_t)(kt * FBN) * HN;
#pragma unroll
        for (int j = 0; j < 4; j++) {
            int lin = tid + j * 256;
            int r = lin >> 4, c = (lin & 15) * 8;
            size_t g = base + (size_t)r * HN + c;
            int so = r * FSTR + c;
            cp16(&Khs[so], Khg + g);
            cp16(&Kls[so], Klg + g);
            cp16(&Vhs[so], Vhg + g);
            cp16(&Vls[so], Vlg + g);
        }
    };

#pragma unroll
    for (int j = 0; j < 8; j++) {
        int lin = tid + j * 256;
        int r = lin >> 4, c = (lin & 15) * 8;
        size_t g = head + (size_t)(row0 + r) * HN + c;
        cp16(&Qh[r * FSTR + c], Qhg + g);
        cp16(&Ql[r * FSTR + c], Qlg + g);
    }
    prefetch(0, 0);
    cp_commit();

    float oacc[16][4];
#pragma unroll
    for (int t = 0; t < 16; t++)
#pragma unroll
        for (int e = 0; e < 4; e++) oacc[t][e] = 0.f;
    float m_i[2] = {-1e30f, -1e30f};
    float l_i[2] = {0.f, 0.f};

    const int a_row = warp * 16 + (lane & 15);
    const int a_kh  = (lane >> 4) * 8;
    const int b_r   = (lane >> 4) * 8 + (lane & 7);
    const int b_kh  = ((lane >> 3) & 1) * 8;
    const int v_row = ((lane >> 3) & 1) * 8 + (lane & 7);
    const int v_col = (lane >> 4) * 8;
    const int gr    = lane >> 2;
    const int gc    = (lane & 3) * 2;
    const int wrow_last = row0 + warp * 16 + 15;

    const int nkt = (row0 + FBM) / FBN;
#pragma unroll 1
    for (int kt = 0; kt < nkt; kt++) {
        const int kr0 = kt * FBN;
        const int s = kt & 1;

        if (kt + 1 < nkt) {
            prefetch(kt + 1, (kt + 1) & 1);
            cp_commit();
            cp_wait<1>();
        } else {
            cp_wait<0>();
        }
        __syncthreads();

        if (kr0 <= wrow_last) {
            __nv_bfloat16* Khs = St + (size_t)s * FA_STAGE_ELEMS;
            __nv_bfloat16* Kls = Khs + FBN * FSTR;
            __nv_bfloat16* Vhs = Kls + FBN * FSTR;
            __nv_bfloat16* Vls = Vhs + FBN * FSTR;

            float sacc[8][4];
#pragma unroll
            for (int t = 0; t < 8; t++)
#pragma unroll
                for (int e = 0; e < 4; e++) sacc[t][e] = 0.f;

#pragma unroll
            for (int kk = 0; kk < 8; kk++) {
                uint32_t aH[4], aL[4];
                ldsm_x4(aH[0], aH[1], aH[2], aH[3],
                        smem_u32(&Qh[a_row * FSTR + kk * 16 + a_kh]));
                ldsm_x4(aL[0], aL[1], aL[2], aL[3],
                        smem_u32(&Ql[a_row * FSTR + kk * 16 + a_kh]));
#pragma unroll
                for (int nt2 = 0; nt2 < 4; nt2++) {
                    uint32_t bh[4], bl[4];
                    ldsm_x4(bh[0], bh[1], bh[2], bh[3],
                            smem_u32(&Khs[(nt2 * 16 + b_r) * FSTR + kk * 16 + b_kh]));
                    ldsm_x4(bl[0], bl[1], bl[2], bl[3],
                            smem_u32(&Kls[(nt2 * 16 + b_r) * FSTR + kk * 16 + b_kh]));
                    mma_bf16(sacc[nt2 * 2], aH, bh);
                    mma_bf16(sacc[nt2 * 2], aH, bl);
                    mma_bf16(sacc[nt2 * 2], aL, bh);
                    mma_bf16(sacc[nt2 * 2 + 1], aH, bh + 2);
                    mma_bf16(sacc[nt2 * 2 + 1], aH, bl + 2);
                    mma_bf16(sacc[nt2 * 2 + 1], aL, bh + 2);
                }
            }

            if (kr0 + FBN - 1 > row0 + warp * 16) {
                int grow0 = row0 + warp * 16 + gr;
#pragma unroll
                for (int t = 0; t < 8; t++) {
                    int colb = kr0 + t * 8 + gc;
                    if (colb     > grow0)     sacc[t][0] = -1e30f;
                    if (colb + 1 > grow0)     sacc[t][1] = -1e30f;
                    if (colb     > grow0 + 8) sacc[t][2] = -1e30f;
                    if (colb + 1 > grow0 + 8) sacc[t][3] = -1e30f;
                }
            }

            float mx0 = -1e30f, mx1 = -1e30f;
#pragma unroll
            for (int t = 0; t < 8; t++) {
                mx0 = fmaxf(mx0, fmaxf(sacc[t][0], sacc[t][1]));
                mx1 = fmaxf(mx1, fmaxf(sacc[t][2], sacc[t][3]));
            }
            mx0 = fmaxf(mx0, __shfl_xor_sync(0xffffffffu, mx0, 1));
            mx0 = fmaxf(mx0, __shfl_xor_sync(0xffffffffu, mx0, 2));
            mx1 = fmaxf(mx1, __shfl_xor_sync(0xffffffffu, mx1, 1));
            mx1 = fmaxf(mx1, __shfl_xor_sync(0xffffffffu, mx1, 2));
            float mn0 = fmaxf(m_i[0], mx0);
            float mn1 = fmaxf(m_i[1], mx1);
            float corr0 = __expf(m_i[0] - mn0);
            float corr1 = __expf(m_i[1] - mn1);

            uint32_t aPh[4][4], aPl[4][4];
            float rs0 = 0.f, rs1 = 0.f;
#pragma unroll
            for (int t = 0; t < 8; t++) {
                float p00 = __expf(sacc[t][0] - mn0);
                float p01 = __expf(sacc[t][1] - mn0);
                float p10 = __expf(sacc[t][2] - mn1);
                float p11 = __expf(sacc[t][3] - mn1);
                rs0 += p00 + p01;
                rs1 += p10 + p11;
                int kc = t >> 1, half = (t & 1) * 2;
                float h00 = __bfloat162float(__float2bfloat16_rn(p00));
                float h01 = __bfloat162float(__float2bfloat16_rn(p01));
                float h10 = __bfloat162float(__float2bfloat16_rn(p10));
                float h11 = __bfloat162float(__float2bfloat16_rn(p11));
                aPh[kc][half]     = pack_bf2(h00, h01);
                aPh[kc][half + 1] = pack_bf2(h10, h11);
                aPl[kc][half]     = pack_bf2(p00 - h00, p01 - h01);
                aPl[kc][half + 1] = pack_bf2(p10 - h10, p11 - h11);
            }
            rs0 += __shfl_xor_sync(0xffffffffu, rs0, 1);
            rs0 += __shfl_xor_sync(0xffffffffu, rs0, 2);
            rs1 += __shfl_xor_sync(0xffffffffu, rs1, 1);
            rs1 += __shfl_xor_sync(0xffffffffu, rs1, 2);
            l_i[0] = l_i[0] * corr0 + rs0;  m_i[0] = mn0;
            l_i[1] = l_i[1] * corr1 + rs1;  m_i[1] = mn1;

#pragma unroll
            for (int t = 0; t < 16; t++) {
                oacc[t][0] *= corr0; oacc[t][1] *= corr0;
                oacc[t][2] *= corr1; oacc[t][3] *= corr1;
            }

#pragma unroll
            for (int kc = 0; kc < 4; kc++) {
#pragma unroll
                for (int nt2 = 0; nt2 < 8; nt2++) {
                    uint32_t bh[4], bl[4];
                    ldsm_x4_t(bh[0], bh[1], bh[2], bh[3],
                              smem_u32(&Vhs[(kc * 16 + v_row) * FSTR + nt2 * 16 + v_col]));
                    ldsm_x4_t(bl[0], bl[1], bl[2], bl[3],
                              smem_u32(&Vls[(kc * 16 + v_row) * FSTR + nt2 * 16 + v_col]));
                    mma_bf16(oacc[nt2 * 2], aPh[kc], bh);
                    mma_bf16(oacc[nt2 * 2], aPh[kc], bl);
                    mma_bf16(oacc[nt2 * 2], aPl[kc], bh);
                    mma_bf16(oacc[nt2 * 2 + 1], aPh[kc], bh + 2);
                    mma_bf16(oacc[nt2 * 2 + 1], aPh[kc], bl + 2);
                    mma_bf16(oacc[nt2 * 2 + 1], aPl[kc], bh + 2);
                }
            }
        }

        __syncthreads();
    }

    // ---- epilogue: normalize, write ctx hi/lo planes [s][b][n*128+d] ----
    {
        float inv0 = 1.0f / l_i[0];
        float inv1 = 1.0f / l_i[1];
        int s0 = row0 + warp * 16 + gr;
        size_t o0 = ((size_t)s0 * BATCH + b) * HID + n * HN;
        size_t o1 = ((size_t)(s0 + 8) * BATCH + b) * HID + n * HN;
#pragma unroll
        for (int t = 0; t < 16; t++) {
            int col = t * 8 + gc;
            float a0 = oacc[t][0] * inv0, a1 = oacc[t][1] * inv0;
            float b0 = oacc[t][2] * inv1, b1 = oacc[t][3] * inv1;
            __nv_bfloat16 ha0 = __float2bfloat16_rn(a0);
            __nv_bfloat16 ha1 = __float2bfloat16_rn(a1);
            __nv_bfloat16 hb0 = __float2bfloat16_rn(b0);
            __nv_bfloat16 hb1 = __float2bfloat16_rn(b1);
            __nv_bfloat162 t2;
            t2.x = ha0; t2.y = ha1; *(__nv_bfloat162*)&Ch[o0 + col] = t2;
            t2.x = hb0; t2.y = hb1; *(__nv_bfloat162*)&Ch[o1 + col] = t2;
            t2.x = __float2bfloat16_rn(a0 - __bfloat162float(ha0));
            t2.y = __float2bfloat16_rn(a1 - __bfloat162float(ha1));
            *(__nv_bfloat162*)&Cl[o0 + col] = t2;
            t2.x = __float2bfloat16_rn(b0 - __bfloat162float(hb0));
            t2.y = __float2bfloat16_rn(b1 - __bfloat162float(hb1));
            *(__nv_bfloat162*)&Cl[o1 + col] = t2;
        }
    }
}

// ---------------------------------------------------------------------------
// Launch
// ---------------------------------------------------------------------------
extern "C" void kernel_launch(void* const* d_in, const int* in_sizes, int n_in,
                              void* d_out, int out_size)
{
    const float* hidden  = (const float*)d_in[0];
    // d_in[1] = attention_mask (causal; handled analytically)
    const float* w_qkv   = (const float*)d_in[2];
    const float* b_qkv   = (const float*)d_in[3];
    const float* w_dense = (const float*)d_in[4];
    const float* b_dense = (const float*)d_in[5];
    float* out = (float*)d_out;

    float *qkv;
    __nv_bfloat16 *qh, *ql, *kh, *kl, *vh, *vl;
    __nv_bfloat16 *hh, *hl, *wqh, *wql, *wdh, *wdl, *ch, *cl;
    cudaGetSymbolAddress((void**)&qkv, g_qkv);
    cudaGetSymbolAddress((void**)&qh,  g_qh);
    cudaGetSymbolAddress((void**)&ql,  g_ql);
    cudaGetSymbolAddress((void**)&kh,  g_kh);
    cudaGetSymbolAddress((void**)&kl,  g_kl);
    cudaGetSymbolAddress((void**)&vh,  g_vh);
    cudaGetSymbolAddress((void**)&vl,  g_vl);
    cudaGetSymbolAddress((void**)&hh,  g_hh);
    cudaGetSymbolAddress((void**)&hl,  g_hl);
    cudaGetSymbolAddress((void**)&wqh, g_wqh);
    cudaGetSymbolAddress((void**)&wql, g_wql);
    cudaGetSymbolAddress((void**)&wdh, g_wdh);
    cudaGetSymbolAddress((void**)&wdl, g_wdl);
    cudaGetSymbolAddress((void**)&ch,  g_ch);
    cudaGetSymbolAddress((void**)&cl,  g_cl);

    cudaFuncSetAttribute(bf16x3_gemm_nt_bias,
                         cudaFuncAttributeMaxDynamicSharedMemorySize, GEMM_SMEM_BYTES);
    cudaFuncSetAttribute(flash_hmma_kernel,
                         cudaFuncAttributeMaxDynamicSharedMemorySize, FA_SMEM_BYTES);

    // 0) pre-split activations & weights into bf16 hi/lo planes
    split_f32_bf16x2<<<(M_ROWS * HID) / 1024, 256>>>(hidden, hh, hl);
    split_f32_bf16x2<<<(QKV_N * HID) / 1024, 256>>>(w_qkv, wqh, wql);
    split_f32_bf16x2<<<(HID * HID) / 1024, 256>>>(w_dense, wdh, wdl);

    // 1) QKV projection (pure bf16x3 tensor-core pipeline)
    bf16x3_gemm_nt_bias<<<dim3(QKV_N / TBN, M_ROWS / TBM), 256, GEMM_SMEM_BYTES>>>(
        hh, hl, wqh, wql, b_qkv, qkv, M_ROWS, QKV_N, HID);

    // 2) Rotary + split into bf16 hi/lo planes [b][n][s][d]
    {
        int total = S_LEN * BATCH * NP * (HN / 2);
        rotary_split_kernel<<<total / 256, 256>>>(qkv, qh, ql, kh, kl, vh, vl);
    }

    // 3) Causal flash attention -> ctx hi/lo planes
    flash_hmma_kernel<<<dim3(S_LEN / FBM, NP, BATCH), 256, FA_SMEM_BYTES>>>(
        qh, ql, kh, kl, vh, vl, ch, cl);

    // 4) Dense projection (pure bf16x3 tensor-core pipeline)
    bf16x3_gemm_nt_bias<<<dim3(HID / TBN, M_ROWS / TBM), 256, GEMM_SMEM_BYTES>>>(
        ch, cl, wdh, wdl, b_dense, out, M_ROWS, HID, HID);
}

// round 11
// speedup vs baseline: 1.0970x; 1.0970x over previous
#include <cuda_runtime.h>
#include <cuda_bf16.h>
#include <math.h>
#include <stdint.h>

// Problem constants
#define S_LEN 2048
#define BATCH 2
#define HID   2048
#define NP    16
#define HN    128
#define M_ROWS (S_LEN*BATCH)     // 4096
#define QKV_N  (3*HID)           // 6144
#define HEAD_ELEMS ((size_t)BATCH * NP * S_LEN * HN)   // 8388608

// ---------------------------------------------------------------------------
// Scratch (device globals; no runtime allocation allowed)
// ---------------------------------------------------------------------------
__device__ float g_qkv[(size_t)M_ROWS * QKV_N];                 // [4096][6144]
__device__ __nv_bfloat16 g_qh[HEAD_ELEMS], g_ql[HEAD_ELEMS];    // [b][n][s][d]
__device__ __nv_bfloat16 g_kh[HEAD_ELEMS], g_kl[HEAD_ELEMS];
__device__ __nv_bfloat16 g_vh[HEAD_ELEMS], g_vl[HEAD_ELEMS];
__device__ __nv_bfloat16 g_hh[(size_t)M_ROWS * HID], g_hl[(size_t)M_ROWS * HID];
__device__ __nv_bfloat16 g_wqh[(size_t)QKV_N * HID], g_wql[(size_t)QKV_N * HID];
__device__ __nv_bfloat16 g_wdh[(size_t)HID * HID],  g_wdl[(size_t)HID * HID];
__device__ __nv_bfloat16 g_ch[(size_t)M_ROWS * HID], g_cl[(size_t)M_ROWS * HID];

// ---------------------------------------------------------------------------
// PTX helpers
// ---------------------------------------------------------------------------
__device__ __forceinline__ uint32_t smem_u32(const void* p) {
    return (uint32_t)__cvta_generic_to_shared(p);
}
__device__ __forceinline__ void ldsm_x4(uint32_t& r0, uint32_t& r1,
                                        uint32_t& r2, uint32_t& r3, uint32_t addr) {
    asm volatile("ldmatrix.sync.aligned.m8n8.x4.shared.b16 {%0,%1,%2,%3}, [%4];"
        : "=r"(r0), "=r"(r1), "=r"(r2), "=r"(r3) : "r"(addr));
}
__device__ __forceinline__ void ldsm_x4_t(uint32_t& r0, uint32_t& r1,
                                          uint32_t& r2, uint32_t& r3, uint32_t addr) {
    asm volatile("ldmatrix.sync.aligned.m8n8.x4.trans.shared.b16 {%0,%1,%2,%3}, [%4];"
        : "=r"(r0), "=r"(r1), "=r"(r2), "=r"(r3) : "r"(addr));
}
__device__ __forceinline__ void mma_bf16(float* d, const uint32_t* a, const uint32_t* b) {
    asm volatile("mma.sync.aligned.m16n8k16.row.col.f32.bf16.bf16.f32 "
        "{%0,%1,%2,%3}, {%4,%5,%6,%7}, {%8,%9}, {%0,%1,%2,%3};"
        : "+f"(d[0]), "+f"(d[1]), "+f"(d[2]), "+f"(d[3])
        : "r"(a[0]), "r"(a[1]), "r"(a[2]), "r"(a[3]), "r"(b[0]), "r"(b[1]));
}
__device__ __forceinline__ uint32_t pack_bf2(float a, float b) {
    __nv_bfloat162 t;
    t.x = __float2bfloat16_rn(a);
    t.y = __float2bfloat16_rn(b);
    return *(uint32_t*)&t;
}
__device__ __forceinline__ void cp16(void* sdst, const void* gsrc) {
    asm volatile("cp.async.cg.shared.global [%0], [%1], 16;\n"
        :: "r"(smem_u32(sdst)), "l"(gsrc));
}
__device__ __forceinline__ void cp_commit() {
    asm volatile("cp.async.commit_group;\n");
}
template <int N>
__device__ __forceinline__ void cp_wait() {
    asm volatile("cp.async.wait_group %0;\n" :: "n"(N));
}

// ---------------------------------------------------------------------------
// fp32 -> bf16 hi/lo split
// ---------------------------------------------------------------------------
__global__ __launch_bounds__(256) void split_f32_bf16x2(
    const float* __restrict__ src,
    __nv_bfloat16* __restrict__ hi, __nv_bfloat16* __restrict__ lo)
{
    size_t i = ((size_t)blockIdx.x * 256 + threadIdx.x) * 4;
    float4 v = *(const float4*)(src + i);
    __nv_bfloat16 h0 = __float2bfloat16_rn(v.x);
    __nv_bfloat16 h1 = __float2bfloat16_rn(v.y);
    __nv_bfloat16 h2 = __float2bfloat16_rn(v.z);
    __nv_bfloat16 h3 = __float2bfloat16_rn(v.w);
    __nv_bfloat162 t;
    t.x = h0; t.y = h1; *(__nv_bfloat162*)(hi + i)     = t;
    t.x = h2; t.y = h3; *(__nv_bfloat162*)(hi + i + 2) = t;
    t.x = __float2bfloat16_rn(v.x - __bfloat162float(h0));
    t.y = __float2bfloat16_rn(v.y - __bfloat162float(h1));
    *(__nv_bfloat162*)(lo + i) = t;
    t.x = __float2bfloat16_rn(v.z - __bfloat162float(h2));
    t.y = __float2bfloat16_rn(v.w - __bfloat162float(h3));
    *(__nv_bfloat162*)(lo + i + 2) = t;
}

// ---------------------------------------------------------------------------
// Pure-bf16x3 GEMM (NT), pre-split operands, 2-stage cp.async pipeline,
// 2 CTAs/SM for issue-slot coverage.
// C[M,N] = (Ah+Al)[M,K] * (Bh+Bl)[N,K]^T + bias  (Ah*Bh + Ah*Bl + Al*Bh)
// BM=BN=128, BK=32, 256 threads (8 warps 4x2), warp tile 32x64.
// ---------------------------------------------------------------------------
#define TBM 128
#define TBN 128
#define TBK 32
#define TSTR 40
#define NSTAGE 2
#define PLANE (TBM*TSTR)                    // 5120 bf16
#define BOFF  (NSTAGE*2*PLANE)              // B matrix offset in smem
#define GEMM_SMEM_BYTES (NSTAGE*2*PLANE*2*2)  // 81920 B  (x2 CTAs = 160 KB/SM)

__global__ __launch_bounds__(256, 2) void bf16x3_gemm_nt_bias(
    const __nv_bfloat16* __restrict__ Ah, const __nv_bfloat16* __restrict__ Al,
    const __nv_bfloat16* __restrict__ Bh, const __nv_bfloat16* __restrict__ Bl,
    const float* __restrict__ bias, float* __restrict__ C,
    int M, int N, int K)
{
    extern __shared__ __nv_bfloat16 smg[];

    const int tid  = threadIdx.x;
    const int bx   = blockIdx.x, by = blockIdx.y;
    const int warp = tid >> 5, lane = tid & 31;
    const int wr   = warp & 3;
    const int wc   = warp >> 2;

    // load mapping: 512 16B-chunks per plane; 2 chunks/thread/plane
    const int r0c = tid >> 2;          // base row (chunk 0)
    const int c0c = (tid & 3) * 8;     // bf16 col

    auto prefetch = [&](int kt, int s) {
        const size_t kof = (size_t)kt * TBK;
#pragma unroll
        for (int j = 0; j < 2; j++) {
            int r = r0c + j * 64;
            int so = r * TSTR + c0c;
            size_t ga = (size_t)(by * TBM + r) * K + kof + c0c;
            size_t gb = (size_t)(bx * TBN + r) * K + kof + c0c;
            cp16(smg + (size_t)(s * 2 + 0) * PLANE + so, Ah + ga);
            cp16(smg + (size_t)(s * 2 + 1) * PLANE + so, Al + ga);
            cp16(smg + BOFF + (size_t)(s * 2 + 0) * PLANE + so, Bh + gb);
            cp16(smg + BOFF + (size_t)(s * 2 + 1) * PLANE + so, Bl + gb);
        }
    };

    float acc[2][8][4];
#pragma unroll
    for (int mi = 0; mi < 2; mi++)
#pragma unroll
        for (int ni = 0; ni < 8; ni++)
#pragma unroll
            for (int e = 0; e < 4; e++) acc[mi][ni][e] = 0.f;

    // ldmatrix lane addressing
    const int a_row = wr * 32 + (lane & 15);
    const int a_kh  = (lane >> 4) * 8;
    const int bg    = lane >> 3;
    const int b_row = wc * 64 + ((bg >> 1) << 3) + (lane & 7);
    const int b_kh  = (bg & 1) * 8;

    auto compute = [&](int s) {
        const __nv_bfloat16* A0 = smg + (size_t)(s * 2 + 0) * PLANE;
        const __nv_bfloat16* A1 = smg + (size_t)(s * 2 + 1) * PLANE;
        const __nv_bfloat16* B0 = smg + BOFF + (size_t)(s * 2 + 0) * PLANE;
        const __nv_bfloat16* B1 = smg + BOFF + (size_t)(s * 2 + 1) * PLANE;
#pragma unroll
        for (int kk = 0; kk < TBK; kk += 16) {
            uint32_t af[2][2][4];
#pragma unroll
            for (int mi = 0; mi < 2; mi++) {
                ldsm_x4(af[0][mi][0], af[0][mi][1], af[0][mi][2], af[0][mi][3],
                        smem_u32(A0 + (a_row + mi * 16) * TSTR + kk + a_kh));
                ldsm_x4(af[1][mi][0], af[1][mi][1], af[1][mi][2], af[1][mi][3],
                        smem_u32(A1 + (a_row + mi * 16) * TSTR + kk + a_kh));
            }
            // process B in ni-pairs to keep register count low (2 CTAs/SM)
#pragma unroll
            for (int np = 0; np < 4; np++) {
                uint32_t b0[4], b1[4];
                ldsm_x4(b0[0], b0[1], b0[2], b0[3],
                        smem_u32(B0 + (b_row + np * 16) * TSTR + kk + b_kh));
                ldsm_x4(b1[0], b1[1], b1[2], b1[3],
                        smem_u32(B1 + (b_row + np * 16) * TSTR + kk + b_kh));
#pragma unroll
                for (int mi = 0; mi < 2; mi++) {
                    mma_bf16(acc[mi][np * 2],     af[0][mi], b0);       // Ah*Bh
                    mma_bf16(acc[mi][np * 2],     af[0][mi], b1);       // Ah*Bl
                    mma_bf16(acc[mi][np * 2],     af[1][mi], b0);       // Al*Bh
                    mma_bf16(acc[mi][np * 2 + 1], af[0][mi], b0 + 2);
                    mma_bf16(acc[mi][np * 2 + 1], af[0][mi], b1 + 2);
                    mma_bf16(acc[mi][np * 2 + 1], af[1][mi], b0 + 2);
                }
            }
        }
    };

    const int nt = K / TBK;
    prefetch(0, 0); cp_commit();
    prefetch(1, 1); cp_commit();
#pragma unroll 1
    for (int kt = 0; kt < nt; kt++) {
        cp_wait<1>();
        __syncthreads();          // stage kt&1 holds chunk kt
        compute(kt & 1);
        __syncthreads();          // all reads of stage kt&1 done
        if (kt + 2 < nt) {
            prefetch(kt + 2, kt & 1);
            cp_commit();
        } else {
            cp_commit();          // keep group count in step
        }
    }

    // epilogue
    const int gr = lane >> 2, gc = (lane & 3) * 2;
#pragma unroll
    for (int mi = 0; mi < 2; mi++) {
        int row = by * TBM + wr * 32 + mi * 16 + gr;
#pragma unroll
        for (int ni = 0; ni < 8; ni++) {
            int col = bx * TBN + wc * 64 + ni * 8 + gc;
            float b0 = bias[col], b1 = bias[col + 1];
            float2 v0, v1;
            v0.x = acc[mi][ni][0] + b0; v0.y = acc[mi][ni][1] + b1;
            v1.x = acc[mi][ni][2] + b0; v1.y = acc[mi][ni][3] + b1;
            *(float2*)&C[(size_t)row * N + col] = v0;
            *(float2*)&C[(size_t)(row + 8) * N + col] = v1;
        }
    }
}

// ---------------------------------------------------------------------------
// Rotary + QKV split/transpose + bf16 hi/lo split.
// ---------------------------------------------------------------------------
__global__ __launch_bounds__(256) void rotary_split_kernel(
    const float* __restrict__ mixed,
    __nv_bfloat16* __restrict__ Qh, __nv_bfloat16* __restrict__ Ql,
    __nv_bfloat16* __restrict__ Kh, __nv_bfloat16* __restrict__ Kl,
    __nv_bfloat16* __restrict__ Vh, __nv_bfloat16* __restrict__ Vl)
{
    int idx = blockIdx.x * blockDim.x + threadIdx.x;
    int i = idx & 63;
    int rest = idx >> 6;
    int n = rest & (NP - 1); rest >>= 4;
    int b = rest & (BATCH - 1);
    int s = rest >> 1;

    const float* src = mixed + (((size_t)(s * BATCH + b)) * NP + n) * (3 * HN);
    size_t dst = (((size_t)b * NP + n) * S_LEN + s) * HN;

    float expo = (float)(2 * i) / (float)HN;
    float freq = powf(1e-4f, expo);
    float ang  = (float)s * freq;
    float sn, cs;
    sincosf(ang, &sn, &cs);

    const float qscale = 0.0883883476483184f;     // 1/sqrt(128)

    float ql_ = src[i],       qr_ = src[i + 64];
    float kl_ = src[128 + i], kr_ = src[192 + i];

    float q0 = (cs * ql_ - sn * qr_) * qscale;
    float q1 = (sn * ql_ + cs * qr_) * qscale;
    float k0 = cs * kl_ - sn * kr_;
    float k1 = sn * kl_ + cs * kr_;
    float v0 = src[256 + i];
    float v1 = src[320 + i];

    __nv_bfloat16 h;
    h = __float2bfloat16_rn(q0); Qh[dst + i] = h;
    Ql[dst + i] = __float2bfloat16_rn(q0 - __bfloat162float(h));
    h = __float2bfloat16_rn(q1); Qh[dst + 64 + i] = h;
    Ql[dst + 64 + i] = __float2bfloat16_rn(q1 - __bfloat162float(h));
    h = __float2bfloat16_rn(k0); Kh[dst + i] = h;
    Kl[dst + i] = __float2bfloat16_rn(k0 - __bfloat162float(h));
    h = __float2bfloat16_rn(k1); Kh[dst + 64 + i] = h;
    Kl[dst + 64 + i] = __float2bfloat16_rn(k1 - __bfloat162float(h));
    h = __float2bfloat16_rn(v0); Vh[dst + i] = h;
    Vl[dst + i] = __float2bfloat16_rn(v0 - __bfloat162float(h));
    h = __float2bfloat16_rn(v1); Vh[dst + 64 + i] = h;
    Vl[dst + 64 + i] = __float2bfloat16_rn(v1 - __bfloat162float(h));
}

// ---------------------------------------------------------------------------
// HMMA flash attention (bf16x3), cp.async double-buffered; ctx out as hi/lo.
// ---------------------------------------------------------------------------
#define FBM 128
#define FBN 64
#define FSTR 136
#define FA_STAGE_ELEMS (4*FBN*FSTR)
#define FA_SMEM_BYTES ((2*FBM*FSTR + 2*FA_STAGE_ELEMS) * 2)   // 208896

__global__ __launch_bounds__(256, 1) void flash_hmma_kernel(
    const __nv_bfloat16* __restrict__ Qhg, const __nv_bfloat16* __restrict__ Qlg,
    const __nv_bfloat16* __restrict__ Khg, const __nv_bfloat16* __restrict__ Klg,
    const __nv_bfloat16* __restrict__ Vhg, const __nv_bfloat16* __restrict__ Vlg,
    __nv_bfloat16* __restrict__ Ch, __nv_bfloat16* __restrict__ Cl)
{
    extern __shared__ __nv_bfloat16 fsm[];
    __nv_bfloat16* Qh = fsm;
    __nv_bfloat16* Ql = Qh + FBM * FSTR;
    __nv_bfloat16* St = Ql + FBM * FSTR;

    const int qt = gridDim.x - 1 - blockIdx.x;
    const int n  = blockIdx.y;
    const int b  = blockIdx.z;
    const int tid  = threadIdx.x;
    const int warp = tid >> 5, lane = tid & 31;

    const size_t head = ((size_t)b * NP + n) * (size_t)S_LEN * HN;
    const int row0 = qt * FBM;

    auto prefetch = [&](int kt, int s) {
        __nv_bfloat16* Khs = St + (size_t)s * FA_STAGE_ELEMS;
        __nv_bfloat16* Kls = Khs + FBN * FSTR;
        __nv_bfloat16* Vhs = Kls + FBN * FSTR;
        __nv_bfloat16* Vls = Vhs + FBN * FSTR;
        size_t base = head + (size_t)(kt * FBN) * HN;
#pragma unroll
        for (int j = 0; j < 4; j++) {
            int lin = tid + j * 256;
            int r = lin >> 4, c = (lin & 15) * 8;
            size_t g = base + (size_t)r * HN + c;
            int so = r * FSTR + c;
            cp16(&Khs[so], Khg + g);
            cp16(&Kls[so], Klg + g);
            cp16(&Vhs[so], Vhg + g);
            cp16(&Vls[so], Vlg + g);
        }
    };

#pragma unroll
    for (int j = 0; j < 8; j++) {
        int lin = tid + j * 256;
        int r = lin >> 4, c = (lin & 15) * 8;
        size_t g = head + (size_t)(row0 + r) * HN + c;
        cp16(&Qh[r * FSTR + c], Qhg + g);
        cp16(&Ql[r * FSTR + c], Qlg + g);
    }
    prefetch(0, 0);
    cp_commit();

    float oacc[16][4];
#pragma unroll
    for (int t = 0; t < 16; t++)
#pragma unroll
        for (int e = 0; e < 4; e++) oacc[t][e] = 0.f;
    float m_i[2] = {-1e30f, -1e30f};
    float l_i[2] = {0.f, 0.f};

    const int a_row = warp * 16 + (lane & 15);
    const int a_kh  = (lane >> 4) * 8;
    const int b_r   = (lane >> 4) * 8 + (lane & 7);
    const int b_kh  = ((lane >> 3) & 1) * 8;
    const int v_row = ((lane >> 3) & 1) * 8 + (lane & 7);
    const int v_col = (lane >> 4) * 8;
    const int gr    = lane >> 2;
    const int gc    = (lane & 3) * 2;
    const int wrow_last = row0 + warp * 16 + 15;

    const int nkt = (row0 + FBM) / FBN;
#pragma unroll 1
    for (int kt = 0; kt < nkt; kt++) {
        const int kr0 = kt * FBN;
        const int s = kt & 1;

        if (kt + 1 < nkt) {
            prefetch(kt + 1, (kt + 1) & 1);
            cp_commit();
            cp_wait<1>();
        } else {
            cp_wait<0>();
        }
        __syncthreads();

        if (kr0 <= wrow_last) {
            __nv_bfloat16* Khs = St + (size_t)s * FA_STAGE_ELEMS;
            __nv_bfloat16* Kls = Khs + FBN * FSTR;
            __nv_bfloat16* Vhs = Kls + FBN * FSTR;
            __nv_bfloat16* Vls = Vhs + FBN * FSTR;

            float sacc[8][4];
#pragma unroll
            for (int t = 0; t < 8; t++)
#pragma unroll
                for (int e = 0; e < 4; e++) sacc[t][e] = 0.f;

#pragma unroll
            for (int kk = 0; kk < 8; kk++) {
                uint32_t aH[4], aL[4];
                ldsm_x4(aH[0], aH[1], aH[2], aH[3],
                        smem_u32(&Qh[a_row * FSTR + kk * 16 + a_kh]));
                ldsm_x4(aL[0], aL[1], aL[2], aL[3],
                        smem_u32(&Ql[a_row * FSTR + kk * 16 + a_kh]));
#pragma unroll
                for (int nt2 = 0; nt2 < 4; nt2++) {
                    uint32_t bh[4], bl[4];
                    ldsm_x4(bh[0], bh[1], bh[2], bh[3],
                            smem_u32(&Khs[(nt2 * 16 + b_r) * FSTR + kk * 16 + b_kh]));
                    ldsm_x4(bl[0], bl[1], bl[2], bl[3],
                            smem_u32(&Kls[(nt2 * 16 + b_r) * FSTR + kk * 16 + b_kh]));
                    mma_bf16(sacc[nt2 * 2], aH, bh);
                    mma_bf16(sacc[nt2 * 2], aH, bl);
                    mma_bf16(sacc[nt2 * 2], aL, bh);
                    mma_bf16(sacc[nt2 * 2 + 1], aH, bh + 2);
                    mma_bf16(sacc[nt2 * 2 + 1], aH, bl + 2);
                    mma_bf16(sacc[nt2 * 2 + 1], aL, bh + 2);
                }
            }

            if (kr0 + FBN - 1 > row0 + warp * 16) {
                int grow0 = row0 + warp * 16 + gr;
#pragma unroll
                for (int t = 0; t < 8; t++) {
                    int colb = kr0 + t * 8 + gc;
                    if (colb     > grow0)     sacc[t][0] = -1e30f;
                    if (colb + 1 > grow0)     sacc[t][1] = -1e30f;
                    if (colb     > grow0 + 8) sacc[t][2] = -1e30f;
                    if (colb + 1 > grow0 + 8) sacc[t][3] = -1e30f;
                }
            }

            float mx0 = -1e30f, mx1 = -1e30f;
#pragma unroll
            for (int t = 0; t < 8; t++) {
                mx0 = fmaxf(mx0, fmaxf(sacc[t][0], sacc[t][1]));
                mx1 = fmaxf(mx1, fmaxf(sacc[t][2], sacc[t][3]));
            }
            mx0 = fmaxf(mx0, __shfl_xor_sync(0xffffffffu, mx0, 1));
            mx0 = fmaxf(mx0, __shfl_xor_sync(0xffffffffu, mx0, 2));
            mx1 = fmaxf(mx1, __shfl_xor_sync(0xffffffffu, mx1, 1));
            mx1 = fmaxf(mx1, __shfl_xor_sync(0xffffffffu, mx1, 2));
            float mn0 = fmaxf(m_i[0], mx0);
            float mn1 = fmaxf(m_i[1], mx1);
            float corr0 = __expf(m_i[0] - mn0);
            float corr1 = __expf(m_i[1] - mn1);

            uint32_t aPh[4][4], aPl[4][4];
            float rs0 = 0.f, rs1 = 0.f;
#pragma unroll
            for (int t = 0; t < 8; t++) {
                float p00 = __expf(sacc[t][0] - mn0);
                float p01 = __expf(sacc[t][1] - mn0);
                float p10 = __expf(sacc[t][2] - mn1);
                float p11 = __expf(sacc[t][3] - mn1);
                rs0 += p00 + p01;
                rs1 += p10 + p11;
                int kc = t >> 1, half = (t & 1) * 2;
                float h00 = __bfloat162float(__float2bfloat16_rn(p00));
                float h01 = __bfloat162float(__float2bfloat16_rn(p01));
                float h10 = __bfloat162float(__float2bfloat16_rn(p10));
                float h11 = __bfloat162float(__float2bfloat16_rn(p11));
                aPh[kc][half]     = pack_bf2(h00, h01);
                aPh[kc][half + 1] = pack_bf2(h10, h11);
                aPl[kc][half]     = pack_bf2(p00 - h00, p01 - h01);
                aPl[kc][half + 1] = pack_bf2(p10 - h10, p11 - h11);
            }
            rs0 += __shfl_xor_sync(0xffffffffu, rs0, 1);
            rs0 += __shfl_xor_sync(0xffffffffu, rs0, 2);
            rs1 += __shfl_xor_sync(0xffffffffu, rs1, 1);
            rs1 += __shfl_xor_sync(0xffffffffu, rs1, 2);
            l_i[0] = l_i[0] * corr0 + rs0;  m_i[0] = mn0;
            l_i[1] = l_i[1] * corr1 + rs1;  m_i[1] = mn1;

#pragma unroll
            for (int t = 0; t < 16; t++) {
                oacc[t][0] *= corr0; oacc[t][1] *= corr0;
                oacc[t][2] *= corr1; oacc[t][3] *= corr1;
            }

#pragma unroll
            for (int kc = 0; kc < 4; kc++) {
#pragma unroll
                for (int nt2 = 0; nt2 < 8; nt2++) {
                    uint32_t bh[4], bl[4];
                    ldsm_x4_t(bh[0], bh[1], bh[2], bh[3],
                              smem_u32(&Vhs[(kc * 16 + v_row) * FSTR + nt2 * 16 + v_col]));
                    ldsm_x4_t(bl[0], bl[1], bl[2], bl[3],
                              smem_u32(&Vls[(kc * 16 + v_row) * FSTR + nt2 * 16 + v_col]));
                    mma_bf16(oacc[nt2 * 2], aPh[kc], bh);
                    mma_bf16(oacc[nt2 * 2], aPh[kc], bl);
                    mma_bf16(oacc[nt2 * 2], aPl[kc], bh);
                    mma_bf16(oacc[nt2 * 2 + 1], aPh[kc], bh + 2);
                    mma_bf16(oacc[nt2 * 2 + 1], aPh[kc], bl + 2);
                    mma_bf16(oacc[nt2 * 2 + 1], aPl[kc], bh + 2);
                }
            }
        }

        __syncthreads();
    }

    {
        float inv0 = 1.0f / l_i[0];
        float inv1 = 1.0f / l_i[1];
        int s0 = row0 + warp * 16 + gr;
        size_t o0 = ((size_t)s0 * BATCH + b) * HID + n * HN;
        size_t o1 = ((size_t)(s0 + 8) * BATCH + b) * HID + n * HN;
#pragma unroll
        for (int t = 0; t < 16; t++) {
            int col = t * 8 + gc;
            float a0 = oacc[t][0] * inv0, a1 = oacc[t][1] * inv0;
            float b0 = oacc[t][2] * inv1, b1 = oacc[t][3] * inv1;
            __nv_bfloat16 ha0 = __float2bfloat16_rn(a0);
            __nv_bfloat16 ha1 = __float2bfloat16_rn(a1);
            __nv_bfloat16 hb0 = __float2bfloat16_rn(b0);
            __nv_bfloat16 hb1 = __float2bfloat16_rn(b1);
            __nv_bfloat162 t2;
            t2.x = ha0; t2.y = ha1; *(__nv_bfloat162*)&Ch[o0 + col] = t2;
            t2.x = hb0; t2.y = hb1; *(__nv_bfloat162*)&Ch[o1 + col] = t2;
            t2.x = __float2bfloat16_rn(a0 - __bfloat162float(ha0));
            t2.y = __float2bfloat16_rn(a1 - __bfloat162float(ha1));
            *(__nv_bfloat162*)&Cl[o0 + col] = t2;
            t2.x = __float2bfloat16_rn(b0 - __bfloat162float(hb0));
            t2.y = __float2bfloat16_rn(b1 - __bfloat162float(hb1));
            *(__nv_bfloat162*)&Cl[o1 + col] = t2;
        }
    }
}

// ---------------------------------------------------------------------------
// Launch
// ---------------------------------------------------------------------------
extern "C" void kernel_launch(void* const* d_in, const int* in_sizes, int n_in,
                              void* d_out, int out_size)
{
    const float* hidden  = (const float*)d_in[0];
    // d_in[1] = attention_mask (causal; handled analytically)
    const float* w_qkv   = (const float*)d_in[2];
    const float* b_qkv   = (const float*)d_in[3];
    const float* w_dense = (const float*)d_in[4];
    const float* b_dense = (const float*)d_in[5];
    float* out = (float*)d_out;

    float *qkv;
    __nv_bfloat16 *qh, *ql, *kh, *kl, *vh, *vl;
    __nv_bfloat16 *hh, *hl, *wqh, *wql, *wdh, *wdl, *ch, *cl;
    cudaGetSymbolAddress((void**)&qkv, g_qkv);
    cudaGetSymbolAddress((void**)&qh,  g_qh);
    cudaGetSymbolAddress((void**)&ql,  g_ql);
    cudaGetSymbolAddress((void**)&kh,  g_kh);
    cudaGetSymbolAddress((void**)&kl,  g_kl);
    cudaGetSymbolAddress((void**)&vh,  g_vh);
    cudaGetSymbolAddress((void**)&vl,  g_vl);
    cudaGetSymbolAddress((void**)&hh,  g_hh);
    cudaGetSymbolAddress((void**)&hl,  g_hl);
    cudaGetSymbolAddress((void**)&wqh, g_wqh);
    cudaGetSymbolAddress((void**)&wql, g_wql);
    cudaGetSymbolAddress((void**)&wdh, g_wdh);
    cudaGetSymbolAddress((void**)&wdl, g_wdl);
    cudaGetSymbolAddress((void**)&ch,  g_ch);
    cudaGetSymbolAddress((void**)&cl,  g_cl);

    cudaFuncSetAttribute(bf16x3_gemm_nt_bias,
                         cudaFuncAttributeMaxDynamicSharedMemorySize, GEMM_SMEM_BYTES);
    cudaFuncSetAttribute(flash_hmma_kernel,
                         cudaFuncAttributeMaxDynamicSharedMemorySize, FA_SMEM_BYTES);

    // 0) pre-split activations & weights into bf16 hi/lo planes
    split_f32_bf16x2<<<(M_ROWS * HID) / 1024, 256>>>(hidden, hh, hl);
    split_f32_bf16x2<<<(QKV_N * HID) / 1024, 256>>>(w_qkv, wqh, wql);
    split_f32_bf16x2<<<(HID * HID) / 1024, 256>>>(w_dense, wdh, wdl);

    // 1) QKV projection (bf16x3 tensor-core pipeline, 2 CTAs/SM)
    bf16x3_gemm_nt_bias<<<dim3(QKV_N / TBN, M_ROWS / TBM), 256, GEMM_SMEM_BYTES>>>(
        hh, hl, wqh, wql, b_qkv, qkv, M_ROWS, QKV_N, HID);

    // 2) Rotary + split into bf16 hi/lo planes [b][n][s][d]
    {
        int total = S_LEN * BATCH * NP * (HN / 2);
        rotary_split_kernel<<<total / 256, 256>>>(qkv, qh, ql, kh, kl, vh, vl);
    }

    // 3) Causal flash attention -> ctx hi/lo planes
    flash_hmma_kernel<<<dim3(S_LEN / FBM, NP, BATCH), 256, FA_SMEM_BYTES>>>(
        qh, ql, kh, kl, vh, vl, ch, cl);

    // 4) Dense projection (bf16x3 tensor-core pipeline, 2 CTAs/SM)
    bf16x3_gemm_nt_bias<<<dim3(HID / TBN, M_ROWS / TBM), 256, GEMM_SMEM_BYTES>>>(
        ch, cl, wdh, wdl, b_dense, out, M_ROWS, HID, HID);
}

// round 12
// speedup vs baseline: 1.2517x; 1.1410x over previous
#include <cuda_runtime.h>
#include <cuda_bf16.h>
#include <math.h>
#include <stdint.h>

// Problem constants
#define S_LEN 2048
#define BATCH 2
#define HID   2048
#define NP    16
#define HN    128
#define M_ROWS (S_LEN*BATCH)     // 4096
#define QKV_N  (3*HID)           // 6144
#define HEAD_ELEMS ((size_t)BATCH * NP * S_LEN * HN)   // 8388608

// ---------------------------------------------------------------------------
// Scratch (device globals; no runtime allocation allowed)
// ---------------------------------------------------------------------------
__device__ float g_qkv[(size_t)M_ROWS * QKV_N];                 // [4096][6144]
__device__ __nv_bfloat16 g_qh[HEAD_ELEMS], g_ql[HEAD_ELEMS];    // [b][n][s][d]
__device__ __nv_bfloat16 g_kh[HEAD_ELEMS], g_kl[HEAD_ELEMS];
__device__ __nv_bfloat16 g_vh[HEAD_ELEMS], g_vl[HEAD_ELEMS];
__device__ __nv_bfloat16 g_hh[(size_t)M_ROWS * HID], g_hl[(size_t)M_ROWS * HID];
__device__ __nv_bfloat16 g_wqh[(size_t)QKV_N * HID], g_wql[(size_t)QKV_N * HID];
__device__ __nv_bfloat16 g_wdh[(size_t)HID * HID],  g_wdl[(size_t)HID * HID];
__device__ __nv_bfloat16 g_ch[(size_t)M_ROWS * HID], g_cl[(size_t)M_ROWS * HID];

// ---------------------------------------------------------------------------
// PTX helpers
// ---------------------------------------------------------------------------
__device__ __forceinline__ uint32_t smem_u32(const void* p) {
    return (uint32_t)__cvta_generic_to_shared(p);
}
__device__ __forceinline__ void ldsm_x4(uint32_t& r0, uint32_t& r1,
                                        uint32_t& r2, uint32_t& r3, uint32_t addr) {
    asm volatile("ldmatrix.sync.aligned.m8n8.x4.shared.b16 {%0,%1,%2,%3}, [%4];"
        : "=r"(r0), "=r"(r1), "=r"(r2), "=r"(r3) : "r"(addr));
}
__device__ __forceinline__ void ldsm_x4_t(uint32_t& r0, uint32_t& r1,
                                          uint32_t& r2, uint32_t& r3, uint32_t addr) {
    asm volatile("ldmatrix.sync.aligned.m8n8.x4.trans.shared.b16 {%0,%1,%2,%3}, [%4];"
        : "=r"(r0), "=r"(r1), "=r"(r2), "=r"(r3) : "r"(addr));
}
__device__ __forceinline__ void mma_bf16(float* d, const uint32_t* a, const uint32_t* b) {
    asm volatile("mma.sync.aligned.m16n8k16.row.col.f32.bf16.bf16.f32 "
        "{%0,%1,%2,%3}, {%4,%5,%6,%7}, {%8,%9}, {%0,%1,%2,%3};"
        : "+f"(d[0]), "+f"(d[1]), "+f"(d[2]), "+f"(d[3])
        : "r"(a[0]), "r"(a[1]), "r"(a[2]), "r"(a[3]), "r"(b[0]), "r"(b[1]));
}
__device__ __forceinline__ uint32_t pack_bf2(float a, float b) {
    __nv_bfloat162 t;
    t.x = __float2bfloat16_rn(a);
    t.y = __float2bfloat16_rn(b);
    return *(uint32_t*)&t;
}
__device__ __forceinline__ void cp16(void* sdst, const void* gsrc) {
    asm volatile("cp.async.cg.shared.global [%0], [%1], 16;\n"
        :: "r"(smem_u32(sdst)), "l"(gsrc));
}
__device__ __forceinline__ void cp_commit() {
    asm volatile("cp.async.commit_group;\n");
}
template <int N>
__device__ __forceinline__ void cp_wait() {
    asm volatile("cp.async.wait_group %0;\n" :: "n"(N));
}

// ---------------------------------------------------------------------------
// fp32 -> bf16 hi/lo split
// ---------------------------------------------------------------------------
__global__ __launch_bounds__(256) void split_f32_bf16x2(
    const float* __restrict__ src,
    __nv_bfloat16* __restrict__ hi, __nv_bfloat16* __restrict__ lo)
{
    size_t i = ((size_t)blockIdx.x * 256 + threadIdx.x) * 4;
    float4 v = *(const float4*)(src + i);
    __nv_bfloat16 h0 = __float2bfloat16_rn(v.x);
    __nv_bfloat16 h1 = __float2bfloat16_rn(v.y);
    __nv_bfloat16 h2 = __float2bfloat16_rn(v.z);
    __nv_bfloat16 h3 = __float2bfloat16_rn(v.w);
    __nv_bfloat162 t;
    t.x = h0; t.y = h1; *(__nv_bfloat162*)(hi + i)     = t;
    t.x = h2; t.y = h3; *(__nv_bfloat162*)(hi + i + 2) = t;
    t.x = __float2bfloat16_rn(v.x - __bfloat162float(h0));
    t.y = __float2bfloat16_rn(v.y - __bfloat162float(h1));
    *(__nv_bfloat162*)(lo + i) = t;
    t.x = __float2bfloat16_rn(v.z - __bfloat162float(h2));
    t.y = __float2bfloat16_rn(v.w - __bfloat162float(h3));
    *(__nv_bfloat162*)(lo + i + 2) = t;
}

// ---------------------------------------------------------------------------
// Pure-bf16x3 GEMM (NT), 3-stage cp.async pipeline, ONE sync per k-tile,
// packed XOR-swizzled smem (stride 32 bf16), 2 CTAs/SM.
// C[M,N] = (Ah+Al)[M,K] * (Bh+Bl)[N,K]^T + bias  (Ah*Bh + Ah*Bl + Al*Bh)
// BM=BN=128, BK=32, 256 threads (8 warps 4x2), warp tile 32x64.
// smem chunk swizzle: 16B chunk c of row r stored at c ^ ((r>>1)&3).
// ---------------------------------------------------------------------------
#define TBM 128
#define TBN 128
#define TBK 32
#define NSTAGE 3
#define PLANE_E (128*32)                     // 4096 bf16 per plane
#define STAGE_E (4*PLANE_E)                  // Ah|Al|Bh|Bl = 16384 bf16 = 32 KB
#define GEMM_SMEM_BYTES (NSTAGE*STAGE_E*2)   // 98304 B (x2 CTAs = 192 KB/SM)

__device__ __forceinline__ int swz_off(int row, int chunk) {
    return row * 32 + ((chunk ^ ((row >> 1) & 3)) << 3);
}

__global__ __launch_bounds__(256, 2) void bf16x3_gemm_nt_bias(
    const __nv_bfloat16* __restrict__ Ah, const __nv_bfloat16* __restrict__ Al,
    const __nv_bfloat16* __restrict__ Bh, const __nv_bfloat16* __restrict__ Bl,
    const float* __restrict__ bias, float* __restrict__ C,
    int M, int N, int K)
{
    extern __shared__ __nv_bfloat16 smg[];

    const int tid  = threadIdx.x;
    const int bx   = blockIdx.x, by = blockIdx.y;
    const int warp = tid >> 5, lane = tid & 31;
    const int wr   = warp & 3;
    const int wc   = warp >> 2;

    auto prefetch = [&](int kt, int s) {
        __nv_bfloat16* st = smg + (size_t)s * STAGE_E;
        const size_t kof = (size_t)kt * TBK;
#pragma unroll
        for (int j = 0; j < 2; j++) {
            int lin = tid + j * 256;          // 512 chunks per plane
            int r = lin >> 2, c = lin & 3;
            int so = swz_off(r, c);
            size_t ga = (size_t)(by * TBM + r) * K + kof + c * 8;
            size_t gb = (size_t)(bx * TBN + r) * K + kof + c * 8;
            cp16(st + so,               Ah + ga);
            cp16(st + PLANE_E + so,     Al + ga);
            cp16(st + 2 * PLANE_E + so, Bh + gb);
            cp16(st + 3 * PLANE_E + so, Bl + gb);
        }
    };

    float acc[2][8][4];
#pragma unroll
    for (int mi = 0; mi < 2; mi++)
#pragma unroll
        for (int ni = 0; ni < 8; ni++)
#pragma unroll
            for (int e = 0; e < 4; e++) acc[mi][ni][e] = 0.f;

    // ldmatrix lane addressing (row, col-half per lane)
    const int a_row = wr * 32 + (lane & 15);
    const int a_kc  = lane >> 4;                          // col chunk offset 0/1
    const int bg    = lane >> 3;
    const int b_row = wc * 64 + ((bg >> 1) << 3) + (lane & 7);
    const int b_kc  = bg & 1;

    auto compute = [&](int s) {
        const __nv_bfloat16* A0 = smg + (size_t)s * STAGE_E;
        const __nv_bfloat16* A1 = A0 + PLANE_E;
        const __nv_bfloat16* B0 = A0 + 2 * PLANE_E;
        const __nv_bfloat16* B1 = A0 + 3 * PLANE_E;
#pragma unroll
        for (int kk = 0; kk < 2; kk++) {                  // k-halves of 16
            uint32_t af[2][2][4];
#pragma unroll
            for (int mi = 0; mi < 2; mi++) {
                int ra = a_row + mi * 16;
                int off = swz_off(ra, kk * 2 + a_kc);
                ldsm_x4(af[0][mi][0], af[0][mi][1], af[0][mi][2], af[0][mi][3],
                        smem_u32(A0 + off));
                ldsm_x4(af[1][mi][0], af[1][mi][1], af[1][mi][2], af[1][mi][3],
                        smem_u32(A1 + off));
            }
#pragma unroll
            for (int np = 0; np < 4; np++) {
                int rb = b_row + np * 16;
                int off = swz_off(rb, kk * 2 + b_kc);
                uint32_t b0[4], b1[4];
                ldsm_x4(b0[0], b0[1], b0[2], b0[3], smem_u32(B0 + off));
                ldsm_x4(b1[0], b1[1], b1[2], b1[3], smem_u32(B1 + off));
#pragma unroll
                for (int mi = 0; mi < 2; mi++) {
                    mma_bf16(acc[mi][np * 2],     af[0][mi], b0);       // Ah*Bh
                    mma_bf16(acc[mi][np * 2],     af[0][mi], b1);       // Ah*Bl
                    mma_bf16(acc[mi][np * 2],     af[1][mi], b0);       // Al*Bh
                    mma_bf16(acc[mi][np * 2 + 1], af[0][mi], b0 + 2);
                    mma_bf16(acc[mi][np * 2 + 1], af[0][mi], b1 + 2);
                    mma_bf16(acc[mi][np * 2 + 1], af[1][mi], b0 + 2);
                }
            }
        }
    };

    const int nt = K / TBK;
    prefetch(0, 0); cp_commit();
    prefetch(1, 1); cp_commit();
#pragma unroll 1
    for (int kt = 0; kt < nt; kt++) {
        cp_wait<1>();
        __syncthreads();                    // stage kt%3 resident; stage (kt-1)%3 free
        if (kt + 2 < nt) prefetch(kt + 2, (kt + 2) % NSTAGE);
        cp_commit();
        compute(kt % NSTAGE);
    }

    // epilogue
    const int gr = lane >> 2, gc = (lane & 3) * 2;
#pragma unroll
    for (int mi = 0; mi < 2; mi++) {
        int row = by * TBM + wr * 32 + mi * 16 + gr;
#pragma unroll
        for (int ni = 0; ni < 8; ni++) {
            int col = bx * TBN + wc * 64 + ni * 8 + gc;
            float b0 = bias[col], b1 = bias[col + 1];
            float2 v0, v1;
            v0.x = acc[mi][ni][0] + b0; v0.y = acc[mi][ni][1] + b1;
            v1.x = acc[mi][ni][2] + b0; v1.y = acc[mi][ni][3] + b1;
            *(float2*)&C[(size_t)row * N + col] = v0;
            *(float2*)&C[(size_t)(row + 8) * N + col] = v1;
        }
    }
}

// ---------------------------------------------------------------------------
// Rotary + QKV split/transpose + bf16 hi/lo split.
// ---------------------------------------------------------------------------
__global__ __launch_bounds__(256) void rotary_split_kernel(
    const float* __restrict__ mixed,
    __nv_bfloat16* __restrict__ Qh, __nv_bfloat16* __restrict__ Ql,
    __nv_bfloat16* __restrict__ Kh, __nv_bfloat16* __restrict__ Kl,
    __nv_bfloat16* __restrict__ Vh, __nv_bfloat16* __restrict__ Vl)
{
    int idx = blockIdx.x * blockDim.x + threadIdx.x;
    int i = idx & 63;
    int rest = idx >> 6;
    int n = rest & (NP - 1); rest >>= 4;
    int b = rest & (BATCH - 1);
    int s = rest >> 1;

    const float* src = mixed + (((size_t)(s * BATCH + b)) * NP + n) * (3 * HN);
    size_t dst = (((size_t)b * NP + n) * S_LEN + s) * HN;

    float expo = (float)(2 * i) / (float)HN;
    float freq = powf(1e-4f, expo);
    float ang  = (float)s * freq;
    float sn, cs;
    sincosf(ang, &sn, &cs);

    const float qscale = 0.0883883476483184f;     // 1/sqrt(128)

    float ql_ = src[i],       qr_ = src[i + 64];
    float kl_ = src[128 + i], kr_ = src[192 + i];

    float q0 = (cs * ql_ - sn * qr_) * qscale;
    float q1 = (sn * ql_ + cs * qr_) * qscale;
    float k0 = cs * kl_ - sn * kr_;
    float k1 = sn * kl_ + cs * kr_;
    float v0 = src[256 + i];
    float v1 = src[320 + i];

    __nv_bfloat16 h;
    h = __float2bfloat16_rn(q0); Qh[dst + i] = h;
    Ql[dst + i] = __float2bfloat16_rn(q0 - __bfloat162float(h));
    h = __float2bfloat16_rn(q1); Qh[dst + 64 + i] = h;
    Ql[dst + 64 + i] = __float2bfloat16_rn(q1 - __bfloat162float(h));
    h = __float2bfloat16_rn(k0); Kh[dst + i] = h;
    Kl[dst + i] = __float2bfloat16_rn(k0 - __bfloat162float(h));
    h = __float2bfloat16_rn(k1); Kh[dst + 64 + i] = h;
    Kl[dst + 64 + i] = __float2bfloat16_rn(k1 - __bfloat162float(h));
    h = __float2bfloat16_rn(v0); Vh[dst + i] = h;
    Vl[dst + i] = __float2bfloat16_rn(v0 - __bfloat162float(h));
    h = __float2bfloat16_rn(v1); Vh[dst + 64 + i] = h;
    Vl[dst + 64 + i] = __float2bfloat16_rn(v1 - __bfloat162float(h));
}

// ---------------------------------------------------------------------------
// HMMA flash attention (bf16x3), cp.async double-buffered; ctx out as hi/lo.
// ---------------------------------------------------------------------------
#define FBM 128
#define FBN 64
#define FSTR 136
#define FA_STAGE_ELEMS (4*FBN*FSTR)
#define FA_SMEM_BYTES ((2*FBM*FSTR + 2*FA_STAGE_ELEMS) * 2)   // 208896

__global__ __launch_bounds__(256, 1) void flash_hmma_kernel(
    const __nv_bfloat16* __restrict__ Qhg, const __nv_bfloat16* __restrict__ Qlg,
    const __nv_bfloat16* __restrict__ Khg, const __nv_bfloat16* __restrict__ Klg,
    const __nv_bfloat16* __restrict__ Vhg, const __nv_bfloat16* __restrict__ Vlg,
    __nv_bfloat16* __restrict__ Ch, __nv_bfloat16* __restrict__ Cl)
{
    extern __shared__ __nv_bfloat16 fsm[];
    __nv_bfloat16* Qh = fsm;
    __nv_bfloat16* Ql = Qh + FBM * FSTR;
    __nv_bfloat16* St = Ql + FBM * FSTR;

    const int qt = gridDim.x - 1 - blockIdx.x;
    const int n  = blockIdx.y;
    const int b  = blockIdx.z;
    const int tid  = threadIdx.x;
    const int warp = tid >> 5, lane = tid & 31;

    const size_t head = ((size_t)b * NP + n) * (size_t)S_LEN * HN;
    const int row0 = qt * FBM;

    auto prefetch = [&](int kt, int s) {
        __nv_bfloat16* Khs = St + (size_t)s * FA_STAGE_ELEMS;
        __nv_bfloat16* Kls = Khs + FBN * FSTR;
        __nv_bfloat16* Vhs = Kls + FBN * FSTR;
        __nv_bfloat16* Vls = Vhs + FBN * FSTR;
        size_t base = head + (size_t)(kt * FBN) * HN;
#pragma unroll
        for (int j = 0; j < 4; j++) {
            int lin = tid + j * 256;
            int r = lin >> 4, c = (lin & 15) * 8;
            size_t g = base + (size_t)r * HN + c;
            int so = r * FSTR + c;
            cp16(&Khs[so], Khg + g);
            cp16(&Kls[so], Klg + g);
            cp16(&Vhs[so], Vhg + g);
            cp16(&Vls[so], Vlg + g);
        }
    };

#pragma unroll
    for (int j = 0; j < 8; j++) {
        int lin = tid + j * 256;
        int r = lin >> 4, c = (lin & 15) * 8;
        size_t g = head + (size_t)(row0 + r) * HN + c;
        cp16(&Qh[r * FSTR + c], Qhg + g);
        cp16(&Ql[r * FSTR + c], Qlg + g);
    }
    prefetch(0, 0);
    cp_commit();

    float oacc[16][4];
#pragma unroll
    for (int t = 0; t < 16; t++)
#pragma unroll
        for (int e = 0; e < 4; e++) oacc[t][e] = 0.f;
    float m_i[2] = {-1e30f, -1e30f};
    float l_i[2] = {0.f, 0.f};

    const int a_row = warp * 16 + (lane & 15);
    const int a_kh  = (lane >> 4) * 8;
    const int b_r   = (lane >> 4) * 8 + (lane & 7);
    const int b_kh  = ((lane >> 3) & 1) * 8;
    const int v_row = ((lane >> 3) & 1) * 8 + (lane & 7);
    const int v_col = (lane >> 4) * 8;
    const int gr    = lane >> 2;
    const int gc    = (lane & 3) * 2;
    const int wrow_last = row0 + warp * 16 + 15;

    const int nkt = (row0 + FBM) / FBN;
#pragma unroll 1
    for (int kt = 0; kt < nkt; kt++) {
        const int kr0 = kt * FBN;
        const int s = kt & 1;

        if (kt + 1 < nkt) {
            prefetch(kt + 1, (kt + 1) & 1);
            cp_commit();
            cp_wait<1>();
        } else {
            cp_wait<0>();
        }
        __syncthreads();

        if (kr0 <= wrow_last) {
            __nv_bfloat16* Khs = St + (size_t)s * FA_STAGE_ELEMS;
            __nv_bfloat16* Kls = Khs + FBN * FSTR;
            __nv_bfloat16* Vhs = Kls + FBN * FSTR;
            __nv_bfloat16* Vls = Vhs + FBN * FSTR;

            float sacc[8][4];
#pragma unroll
            for (int t = 0; t < 8; t++)
#pragma unroll
                for (int e = 0; e < 4; e++) sacc[t][e] = 0.f;

#pragma unroll
            for (int kk = 0; kk < 8; kk++) {
                uint32_t aH[4], aL[4];
                ldsm_x4(aH[0], aH[1], aH[2], aH[3],
                        smem_u32(&Qh[a_row * FSTR + kk * 16 + a_kh]));
                ldsm_x4(aL[0], aL[1], aL[2], aL[3],
                        smem_u32(&Ql[a_row * FSTR + kk * 16 + a_kh]));
#pragma unroll
                for (int nt2 = 0; nt2 < 4; nt2++) {
                    uint32_t bh[4], bl[4];
                    ldsm_x4(bh[0], bh[1], bh[2], bh[3],
                            smem_u32(&Khs[(nt2 * 16 + b_r) * FSTR + kk * 16 + b_kh]));
                    ldsm_x4(bl[0], bl[1], bl[2], bl[3],
                            smem_u32(&Kls[(nt2 * 16 + b_r) * FSTR + kk * 16 + b_kh]));
                    mma_bf16(sacc[nt2 * 2], aH, bh);
                    mma_bf16(sacc[nt2 * 2], aH, bl);
                    mma_bf16(sacc[nt2 * 2], aL, bh);
                    mma_bf16(sacc[nt2 * 2 + 1], aH, bh + 2);
                    mma_bf16(sacc[nt2 * 2 + 1], aH, bl + 2);
                    mma_bf16(sacc[nt2 * 2 + 1], aL, bh + 2);
                }
            }

            if (kr0 + FBN - 1 > row0 + warp * 16) {
                int grow0 = row0 + warp * 16 + gr;
#pragma unroll
                for (int t = 0; t < 8; t++) {
                    int colb = kr0 + t * 8 + gc;
                    if (colb     > grow0)     sacc[t][0] = -1e30f;
                    if (colb + 1 > grow0)     sacc[t][1] = -1e30f;
                    if (colb     > grow0 + 8) sacc[t][2] = -1e30f;
                    if (colb + 1 > grow0 + 8) sacc[t][3] = -1e30f;
                }
            }

            float mx0 = -1e30f, mx1 = -1e30f;
#pragma unroll
            for (int t = 0; t < 8; t++) {
                mx0 = fmaxf(mx0, fmaxf(sacc[t][0], sacc[t][1]));
                mx1 = fmaxf(mx1, fmaxf(sacc[t][2], sacc[t][3]));
            }
            mx0 = fmaxf(mx0, __shfl_xor_sync(0xffffffffu, mx0, 1));
            mx0 = fmaxf(mx0, __shfl_xor_sync(0xffffffffu, mx0, 2));
            mx1 = fmaxf(mx1, __shfl_xor_sync(0xffffffffu, mx1, 1));
            mx1 = fmaxf(mx1, __shfl_xor_sync(0xffffffffu, mx1, 2));
            float mn0 = fmaxf(m_i[0], mx0);
            float mn1 = fmaxf(m_i[1], mx1);
            float corr0 = __expf(m_i[0] - mn0);
            float corr1 = __expf(m_i[1] - mn1);

            uint32_t aPh[4][4], aPl[4][4];
            float rs0 = 0.f, rs1 = 0.f;
#pragma unroll
            for (int t = 0; t < 8; t++) {
                float p00 = __expf(sacc[t][0] - mn0);
                float p01 = __expf(sacc[t][1] - mn0);
                float p10 = __expf(sacc[t][2] - mn1);
                float p11 = __expf(sacc[t][3] - mn1);
                rs0 += p00 + p01;
                rs1 += p10 + p11;
                int kc = t >> 1, half = (t & 1) * 2;
                float h00 = __bfloat162float(__float2bfloat16_rn(p00));
                float h01 = __bfloat162float(__float2bfloat16_rn(p01));
                float h10 = __bfloat162float(__float2bfloat16_rn(p10));
                float h11 = __bfloat162float(__float2bfloat16_rn(p11));
                aPh[kc][half]     = pack_bf2(h00, h01);
                aPh[kc][half + 1] = pack_bf2(h10, h11);
                aPl[kc][half]     = pack_bf2(p00 - h00, p01 - h01);
                aPl[kc][half + 1] = pack_bf2(p10 - h10, p11 - h11);
            }
            rs0 += __shfl_xor_sync(0xffffffffu, rs0, 1);
            rs0 += __shfl_xor_sync(0xffffffffu, rs0, 2);
            rs1 += __shfl_xor_sync(0xffffffffu, rs1, 1);
            rs1 += __shfl_xor_sync(0xffffffffu, rs1, 2);
            l_i[0] = l_i[0] * corr0 + rs0;  m_i[0] = mn0;
            l_i[1] = l_i[1] * corr1 + rs1;  m_i[1] = mn1;

#pragma unroll
            for (int t = 0; t < 16; t++) {
                oacc[t][0] *= corr0; oacc[t][1] *= corr0;
                oacc[t][2] *= corr1; oacc[t][3] *= corr1;
            }

#pragma unroll
            for (int kc = 0; kc < 4; kc++) {
#pragma unroll
                for (int nt2 = 0; nt2 < 8; nt2++) {
                    uint32_t bh[4], bl[4];
                    ldsm_x4_t(bh[0], bh[1], bh[2], bh[3],
                              smem_u32(&Vhs[(kc * 16 + v_row) * FSTR + nt2 * 16 + v_col]));
                    ldsm_x4_t(bl[0], bl[1], bl[2], bl[3],
                              smem_u32(&Vls[(kc * 16 + v_row) * FSTR + nt2 * 16 + v_col]));
                    mma_bf16(oacc[nt2 * 2], aPh[kc], bh);
                    mma_bf16(oacc[nt2 * 2], aPh[kc], bl);
                    mma_bf16(oacc[nt2 * 2], aPl[kc], bh);
                    mma_bf16(oacc[nt2 * 2 + 1], aPh[kc], bh + 2);
                    mma_bf16(oacc[nt2 * 2 + 1], aPh[kc], bl + 2);
                    mma_bf16(oacc[nt2 * 2 + 1], aPl[kc], bh + 2);
                }
            }
        }

        __syncthreads();
    }

    {
        float inv0 = 1.0f / l_i[0];
        float inv1 = 1.0f / l_i[1];
        int s0 = row0 + warp * 16 + gr;
        size_t o0 = ((size_t)s0 * BATCH + b) * HID + n * HN;
        size_t o1 = ((size_t)(s0 + 8) * BATCH + b) * HID + n * HN;
#pragma unroll
        for (int t = 0; t < 16; t++) {
            int col = t * 8 + gc;
            float a0 = oacc[t][0] * inv0, a1 = oacc[t][1] * inv0;
            float b0 = oacc[t][2] * inv1, b1 = oacc[t][3] * inv1;
            __nv_bfloat16 ha0 = __float2bfloat16_rn(a0);
            __nv_bfloat16 ha1 = __float2bfloat16_rn(a1);
            __nv_bfloat16 hb0 = __float2bfloat16_rn(b0);
            __nv_bfloat16 hb1 = __float2bfloat16_rn(b1);
            __nv_bfloat162 t2;
            t2.x = ha0; t2.y = ha1; *(__nv_bfloat162*)&Ch[o0 + col] = t2;
            t2.x = hb0; t2.y = hb1; *(__nv_bfloat162*)&Ch[o1 + col] = t2;
            t2.x = __float2bfloat16_rn(a0 - __bfloat162float(ha0));
            t2.y = __float2bfloat16_rn(a1 - __bfloat162float(ha1));
            *(__nv_bfloat162*)&Cl[o0 + col] = t2;
            t2.x = __float2bfloat16_rn(b0 - __bfloat162float(hb0));
            t2.y = __float2bfloat16_rn(b1 - __bfloat162float(hb1));
            *(__nv_bfloat162*)&Cl[o1 + col] = t2;
        }
    }
}

// ---------------------------------------------------------------------------
// Launch
// ---------------------------------------------------------------------------
extern "C" void kernel_launch(void* const* d_in, const int* in_sizes, int n_in,
                              void* d_out, int out_size)
{
    const float* hidden  = (const float*)d_in[0];
    // d_in[1] = attention_mask (causal; handled analytically)
    const float* w_qkv   = (const float*)d_in[2];
    const float* b_qkv   = (const float*)d_in[3];
    const float* w_dense = (const float*)d_in[4];
    const float* b_dense = (const float*)d_in[5];
    float* out = (float*)d_out;

    float *qkv;
    __nv_bfloat16 *qh, *ql, *kh, *kl, *vh, *vl;
    __nv_bfloat16 *hh, *hl, *wqh, *wql, *wdh, *wdl, *ch, *cl;
    cudaGetSymbolAddress((void**)&qkv, g_qkv);
    cudaGetSymbolAddress((void**)&qh,  g_qh);
    cudaGetSymbolAddress((void**)&ql,  g_ql);
    cudaGetSymbolAddress((void**)&kh,  g_kh);
    cudaGetSymbolAddress((void**)&kl,  g_kl);
    cudaGetSymbolAddress((void**)&vh,  g_vh);
    cudaGetSymbolAddress((void**)&vl,  g_vl);
    cudaGetSymbolAddress((void**)&hh,  g_hh);
    cudaGetSymbolAddress((void**)&hl,  g_hl);
    cudaGetSymbolAddress((void**)&wqh, g_wqh);
    cudaGetSymbolAddress((void**)&wql, g_wql);
    cudaGetSymbolAddress((void**)&wdh, g_wdh);
    cudaGetSymbolAddress((void**)&wdl, g_wdl);
    cudaGetSymbolAddress((void**)&ch,  g_ch);
    cudaGetSymbolAddress((void**)&cl,  g_cl);

    cudaFuncSetAttribute(bf16x3_gemm_nt_bias,
                         cudaFuncAttributeMaxDynamicSharedMemorySize, GEMM_SMEM_BYTES);
    cudaFuncSetAttribute(flash_hmma_kernel,
                         cudaFuncAttributeMaxDynamicSharedMemorySize, FA_SMEM_BYTES);

    // 0) pre-split activations & weights into bf16 hi/lo planes
    split_f32_bf16x2<<<(M_ROWS * HID) / 1024, 256>>>(hidden, hh, hl);
    split_f32_bf16x2<<<(QKV_N * HID) / 1024, 256>>>(w_qkv, wqh, wql);
    split_f32_bf16x2<<<(HID * HID) / 1024, 256>>>(w_dense, wdh, wdl);

    // 1) QKV projection (bf16x3 tensor-core pipeline, 3-stage, 2 CTAs/SM)
    bf16x3_gemm_nt_bias<<<dim3(QKV_N / TBN, M_ROWS / TBM), 256, GEMM_SMEM_BYTES>>>(
        hh, hl, wqh, wql, b_qkv, qkv, M_ROWS, QKV_N, HID);

    // 2) Rotary + split into bf16 hi/lo planes [b][n][s][d]
    {
        int total = S_LEN * BATCH * NP * (HN / 2);
        rotary_split_kernel<<<total / 256, 256>>>(qkv, qh, ql, kh, kl, vh, vl);
    }

    // 3) Causal flash attention -> ctx hi/lo planes
    flash_hmma_kernel<<<dim3(S_LEN / FBM, NP, BATCH), 256, FA_SMEM_BYTES>>>(
        qh, ql, kh, kl, vh, vl, ch, cl);

    // 4) Dense projection (bf16x3 tensor-core pipeline, 3-stage, 2 CTAs/SM)
    bf16x3_gemm_nt_bias<<<dim3(HID / TBN, M_ROWS / TBM), 256, GEMM_SMEM_BYTES>>>(
        ch, cl, wdh, wdl, b_dense, out, M_ROWS, HID, HID);
}

// round 14
// speedup vs baseline: 1.2743x; 1.0181x over previous
#include <cuda_runtime.h>
#include <cuda_bf16.h>
#include <math.h>
#include <stdint.h>

// Problem constants
#define S_LEN 2048
#define BATCH 2
#define HID   2048
#define NP    16
#define HN    128
#define M_ROWS (S_LEN*BATCH)     // 4096
#define QKV_N  (3*HID)           // 6144
#define HEAD_ELEMS ((size_t)BATCH * NP * S_LEN * HN)   // 8388608

// ---------------------------------------------------------------------------
// Scratch (device globals; no runtime allocation allowed)
// ---------------------------------------------------------------------------
__device__ __nv_bfloat16 g_qh[HEAD_ELEMS], g_ql[HEAD_ELEMS];    // [b][n][s][d]
__device__ __nv_bfloat16 g_kh[HEAD_ELEMS], g_kl[HEAD_ELEMS];
__device__ __nv_bfloat16 g_vh[HEAD_ELEMS], g_vl[HEAD_ELEMS];
__device__ __nv_bfloat16 g_hh[(size_t)M_ROWS * HID], g_hl[(size_t)M_ROWS * HID];
__device__ __nv_bfloat16 g_wqh[(size_t)QKV_N * HID], g_wql[(size_t)QKV_N * HID];
__device__ __nv_bfloat16 g_wdh[(size_t)HID * HID],  g_wdl[(size_t)HID * HID];
__device__ __nv_bfloat16 g_ch[(size_t)M_ROWS * HID], g_cl[(size_t)M_ROWS * HID];
__device__ float2 g_rottab[S_LEN * 64];                         // (cos,sin)[s][i]

// ---------------------------------------------------------------------------
// PTX helpers
// ---------------------------------------------------------------------------
__device__ __forceinline__ uint32_t smem_u32(const void* p) {
    return (uint32_t)__cvta_generic_to_shared(p);
}
__device__ __forceinline__ void ldsm_x4(uint32_t& r0, uint32_t& r1,
                                        uint32_t& r2, uint32_t& r3, uint32_t addr) {
    asm volatile("ldmatrix.sync.aligned.m8n8.x4.shared.b16 {%0,%1,%2,%3}, [%4];"
        : "=r"(r0), "=r"(r1), "=r"(r2), "=r"(r3) : "r"(addr));
}
__device__ __forceinline__ void ldsm_x4_t(uint32_t& r0, uint32_t& r1,
                                          uint32_t& r2, uint32_t& r3, uint32_t addr) {
    asm volatile("ldmatrix.sync.aligned.m8n8.x4.trans.shared.b16 {%0,%1,%2,%3}, [%4];"
        : "=r"(r0), "=r"(r1), "=r"(r2), "=r"(r3) : "r"(addr));
}
__device__ __forceinline__ void mma_bf16(float* d, const uint32_t* a, const uint32_t* b) {
    asm volatile("mma.sync.aligned.m16n8k16.row.col.f32.bf16.bf16.f32 "
        "{%0,%1,%2,%3}, {%4,%5,%6,%7}, {%8,%9}, {%0,%1,%2,%3};"
        : "+f"(d[0]), "+f"(d[1]), "+f"(d[2]), "+f"(d[3])
        : "r"(a[0]), "r"(a[1]), "r"(a[2]), "r"(a[3]), "r"(b[0]), "r"(b[1]));
}
__device__ __forceinline__ uint32_t pack_bf2(float a, float b) {
    __nv_bfloat162 t;
    t.x = __float2bfloat16_rn(a);
    t.y = __float2bfloat16_rn(b);
    return *(uint32_t*)&t;
}
__device__ __forceinline__ void cp16(void* sdst, const void* gsrc) {
    asm volatile("cp.async.cg.shared.global [%0], [%1], 16;\n"
        :: "r"(smem_u32(sdst)), "l"(gsrc));
}
__device__ __forceinline__ void cp_commit() {
    asm volatile("cp.async.commit_group;\n");
}
template <int N>
__device__ __forceinline__ void cp_wait() {
    asm volatile("cp.async.wait_group %0;\n" :: "n"(N));
}
__device__ __forceinline__ void split_store(__nv_bfloat16* H, __nv_bfloat16* L,
                                            size_t idx, float v) {
    __nv_bfloat16 h = __float2bfloat16_rn(v);
    H[idx] = h;
    L[idx] = __float2bfloat16_rn(v - __bfloat162float(h));
}

// ---------------------------------------------------------------------------
// rotary (cos,sin) table: [s][i], i in [0,64)
// ---------------------------------------------------------------------------
__global__ __launch_bounds__(256) void rottab_kernel(float2* __restrict__ tab) {
    int idx = blockIdx.x * 256 + threadIdx.x;      // 131072 total
    int s = idx >> 6, i = idx & 63;
    float expo = (float)(2 * i) / (float)HN;
    float freq = powf(1e-4f, expo);
    float ang  = (float)s * freq;
    float sn, cs;
    sincosf(ang, &sn, &cs);
    tab[idx] = make_float2(cs, sn);
}

// ---------------------------------------------------------------------------
// fp32 -> bf16 hi/lo split
// ---------------------------------------------------------------------------
__global__ __launch_bounds__(256) void split_f32_bf16x2(
    const float* __restrict__ src,
    __nv_bfloat16* __restrict__ hi, __nv_bfloat16* __restrict__ lo)
{
    size_t i = ((size_t)blockIdx.x * 256 + threadIdx.x) * 4;
    float4 v = *(const float4*)(src + i);
    __nv_bfloat16 h0 = __float2bfloat16_rn(v.x);
    __nv_bfloat16 h1 = __float2bfloat16_rn(v.y);
    __nv_bfloat16 h2 = __float2bfloat16_rn(v.z);
    __nv_bfloat16 h3 = __float2bfloat16_rn(v.w);
    __nv_bfloat162 t;
    t.x = h0; t.y = h1; *(__nv_bfloat162*)(hi + i)     = t;
    t.x = h2; t.y = h3; *(__nv_bfloat162*)(hi + i + 2) = t;
    t.x = __float2bfloat16_rn(v.x - __bfloat162float(h0));
    t.y = __float2bfloat16_rn(v.y - __bfloat162float(h1));
    *(__nv_bfloat162*)(lo + i) = t;
    t.x = __float2bfloat16_rn(v.z - __bfloat162float(h2));
    t.y = __float2bfloat16_rn(v.w - __bfloat162float(h3));
    *(__nv_bfloat162*)(lo + i + 2) = t;
}

// ---------------------------------------------------------------------------
// Pure-bf16x3 GEMM (NT), 3-stage cp.async pipeline, ONE sync per k-tile,
// packed XOR-swizzled smem (stride 32 bf16), 2 CTAs/SM.
// FUSE=0: plain fp32 C (+bias).  FUSE=1: QKV epilogue — stage tile in smem,
// apply rotary (table) + qscale, split to bf16 hi/lo planes [b][n][s][d].
// ---------------------------------------------------------------------------
#define TBM 128
#define TBN 128
#define TBK 32
#define NSTAGE 3
#define PLANE_E (128*32)                     // 4096 bf16 per plane
#define STAGE_E (4*PLANE_E)                  // Ah|Al|Bh|Bl = 16384 bf16 = 32 KB
#define GEMM_SMEM_BYTES (NSTAGE*STAGE_E*2)   // 98304 B (x2 CTAs = 192 KB/SM)
#define EPI_STR 136                          // fp32 epilogue smem stride

__device__ __forceinline__ int swz_off(int row, int chunk) {
    return row * 32 + ((chunk ^ ((row >> 1) & 3)) << 3);
}

template <int FUSE>
__global__ __launch_bounds__(256, 2) void bf16x3_gemm_nt(
    const __nv_bfloat16* __restrict__ Ah, const __nv_bfloat16* __restrict__ Al,
    const __nv_bfloat16* __restrict__ Bh, const __nv_bfloat16* __restrict__ Bl,
    const float* __restrict__ bias, float* __restrict__ C,
    const float2* __restrict__ rottab,
    __nv_bfloat16* __restrict__ Qh, __nv_bfloat16* __restrict__ Ql,
    __nv_bfloat16* __restrict__ Kh, __nv_bfloat16* __restrict__ Kl,
    __nv_bfloat16* __restrict__ Vh, __nv_bfloat16* __restrict__ Vl,
    int M, int N, int K)
{
    extern __shared__ __nv_bfloat16 smg[];

    const int tid  = threadIdx.x;
    const int bx   = blockIdx.x, by = blockIdx.y;
    const int warp = tid >> 5, lane = tid & 31;
    const int wr   = warp & 3;
    const int wc   = warp >> 2;

    auto prefetch = [&](int kt, int s) {
        __nv_bfloat16* st = smg + (size_t)s * STAGE_E;
        const size_t kof = (size_t)kt * TBK;
#pragma unroll
        for (int j = 0; j < 2; j++) {
            int lin = tid + j * 256;          // 512 chunks per plane
            int r = lin >> 2, c = lin & 3;
            int so = swz_off(r, c);
            size_t ga = (size_t)(by * TBM + r) * K + kof + c * 8;
            size_t gb = (size_t)(bx * TBN + r) * K + kof + c * 8;
            cp16(st + so,               Ah + ga);
            cp16(st + PLANE_E + so,     Al + ga);
            cp16(st + 2 * PLANE_E + so, Bh + gb);
            cp16(st + 3 * PLANE_E + so, Bl + gb);
        }
    };

    float acc[2][8][4];
#pragma unroll
    for (int mi = 0; mi < 2; mi++)
#pragma unroll
        for (int ni = 0; ni < 8; ni++)
#pragma unroll
            for (int e = 0; e < 4; e++) acc[mi][ni][e] = 0.f;

    const int a_row = wr * 32 + (lane & 15);
    const int a_kc  = lane >> 4;
    const int bg    = lane >> 3;
    const int b_row = wc * 64 + ((bg >> 1) << 3) + (lane & 7);
    const int b_kc  = bg & 1;

    auto compute = [&](int s) {
        const __nv_bfloat16* A0 = smg + (size_t)s * STAGE_E;
        const __nv_bfloat16* A1 = A0 + PLANE_E;
        const __nv_bfloat16* B0 = A0 + 2 * PLANE_E;
        const __nv_bfloat16* B1 = A0 + 3 * PLANE_E;
#pragma unroll
        for (int kk = 0; kk < 2; kk++) {
            uint32_t af[2][2][4];
#pragma unroll
            for (int mi = 0; mi < 2; mi++) {
                int ra = a_row + mi * 16;
                int off = swz_off(ra, kk * 2 + a_kc);
                ldsm_x4(af[0][mi][0], af[0][mi][1], af[0][mi][2], af[0][mi][3],
                        smem_u32(A0 + off));
                ldsm_x4(af[1][mi][0], af[1][mi][1], af[1][mi][2], af[1][mi][3],
                        smem_u32(A1 + off));
            }
#pragma unroll
            for (int np = 0; np < 4; np++) {
                int rb = b_row + np * 16;
                int off = swz_off(rb, kk * 2 + b_kc);
                uint32_t b0[4], b1[4];
                ldsm_x4(b0[0], b0[1], b0[2], b0[3], smem_u32(B0 + off));
                ldsm_x4(b1[0], b1[1], b1[2], b1[3], smem_u32(B1 + off));
#pragma unroll
                for (int mi = 0; mi < 2; mi++) {
                    mma_bf16(acc[mi][np * 2],     af[0][mi], b0);       // Ah*Bh
                    mma_bf16(acc[mi][np * 2],     af[0][mi], b1);       // Ah*Bl
                    mma_bf16(acc[mi][np * 2],     af[1][mi], b0);       // Al*Bh
                    mma_bf16(acc[mi][np * 2 + 1], af[0][mi], b0 + 2);
                    mma_bf16(acc[mi][np * 2 + 1], af[0][mi], b1 + 2);
                    mma_bf16(acc[mi][np * 2 + 1], af[1][mi], b0 + 2);
                }
            }
        }
    };

    const int nt = K / TBK;
    prefetch(0, 0); cp_commit();
    prefetch(1, 1); cp_commit();
#pragma unroll 1
    for (int kt = 0; kt < nt; kt++) {
        cp_wait<1>();
        __syncthreads();
        if (kt + 2 < nt) prefetch(kt + 2, (kt + 2) % NSTAGE);
        cp_commit();
        compute(kt % NSTAGE);
    }

    const int gr = lane >> 2, gc = (lane & 3) * 2;

    if (FUSE == 0) {
        // ---- plain epilogue: bias + fp32 C ----
#pragma unroll
        for (int mi = 0; mi < 2; mi++) {
            int row = by * TBM + wr * 32 + mi * 16 + gr;
#pragma unroll
            for (int ni = 0; ni < 8; ni++) {
                int col = bx * TBN + wc * 64 + ni * 8 + gc;
                float b0 = bias[col], b1 = bias[col + 1];
                float2 v0, v1;
                v0.x = acc[mi][ni][0] + b0; v0.y = acc[mi][ni][1] + b1;
                v1.x = acc[mi][ni][2] + b0; v1.y = acc[mi][ni][3] + b1;
                *(float2*)&C[(size_t)row * N + col] = v0;
                *(float2*)&C[(size_t)(row + 8) * N + col] = v1;
            }
        }
    } else {
        // ---- fused QKV epilogue: stage tile (+bias) in smem fp32 ----
        __syncthreads();    // all compute + smem reads done; reuse smem
        float* sc = (float*)smg;            // [128][EPI_STR]
#pragma unroll
        for (int mi = 0; mi < 2; mi++) {
            int row = wr * 32 + mi * 16 + gr;
#pragma unroll
            for (int ni = 0; ni < 8; ni++) {
                int col = wc * 64 + ni * 8 + gc;
                int gcol = bx * TBN + col;
                float b0 = bias[gcol], b1 = bias[gcol + 1];
                sc[row * EPI_STR + col]           = acc[mi][ni][0] + b0;
                sc[row * EPI_STR + col + 1]       = acc[mi][ni][1] + b1;
                sc[(row + 8) * EPI_STR + col]     = acc[mi][ni][2] + b0;
                sc[(row + 8) * EPI_STR + col + 1] = acc[mi][ni][3] + b1;
            }
        }
        __syncthreads();

        const int type = bx % 3;            // 0=q, 1=k, 2=v
        const int n    = bx / 3;
        const float qscale = 0.0883883476483184f;   // 1/sqrt(128)

        if (type < 2) {
            __nv_bfloat16* H = (type == 0) ? Qh : Kh;
            __nv_bfloat16* L = (type == 0) ? Ql : Kl;
#pragma unroll 4
            for (int j = 0; j < 32; j++) {
                int p = tid + j * 256;      // 0..8191
                int r = p >> 6;
                int i = p & 63;
                int grow = by * TBM + r;    // s*BATCH + b
                int s = grow >> 1, bb = grow & 1;
                float Lv = sc[r * EPI_STR + i];
                float Rv = sc[r * EPI_STR + i + 64];
                float2 cssn = rottab[s * 64 + i];
                float x0 = cssn.x * Lv - cssn.y * Rv;
                float x1 = cssn.y * Lv + cssn.x * Rv;
                if (type == 0) { x0 *= qscale; x1 *= qscale; }
                size_t dst = (((size_t)bb * NP + n) * S_LEN + s) * HN;
                split_store(H, L, dst + i,      x0);
                split_store(H, L, dst + i + 64, x1);
            }
        } else {
#pragma unroll 4
            for (int j = 0; j < 64; j++) {
                int p = tid + j * 256;      // 0..16383
                int r = p >> 7;
                int c = p & 127;
                int grow = by * TBM + r;
                int s = grow >> 1, bb = grow & 1;
                float x = sc[r * EPI_STR + c];
                size_t dst = (((size_t)bb * NP + n) * S_LEN + s) * HN + c;
                split_store(Vh, Vl, dst, x);
            }
        }
    }
}

// ---------------------------------------------------------------------------
// HMMA flash attention (bf16x3), cp.async double-buffered; ctx out as hi/lo.
// ---------------------------------------------------------------------------
#define FBM 128
#define FBN 64
#define FSTR 136
#define FA_STAGE_ELEMS (4*FBN*FSTR)
#define FA_SMEM_BYTES ((2*FBM*FSTR + 2*FA_STAGE_ELEMS) * 2)   // 208896

__global__ __launch_bounds__(256, 1) void flash_hmma_kernel(
    const __nv_bfloat16* __restrict__ Qhg, const __nv_bfloat16* __restrict__ Qlg,
    const __nv_bfloat16* __restrict__ Khg, const __nv_bfloat16* __restrict__ Klg,
    const __nv_bfloat16* __restrict__ Vhg, const __nv_bfloat16* __restrict__ Vlg,
    __nv_bfloat16* __restrict__ Ch, __nv_bfloat16* __restrict__ Cl)
{
    extern __shared__ __nv_bfloat16 fsm[];
    __nv_bfloat16* Qh = fsm;
    __nv_bfloat16* Ql = Qh + FBM * FSTR;
    __nv_bfloat16* St = Ql + FBM * FSTR;

    const int qt = gridDim.x - 1 - blockIdx.x;
    const int n  = blockIdx.y;
    const int b  = blockIdx.z;
    const int tid  = threadIdx.x;
    const int warp = tid >> 5, lane = tid & 31;

    const size_t head = ((size_t)b * NP + n) * (size_t)S_LEN * HN;
    const int row0 = qt * FBM;

    auto prefetch = [&](int kt, int s) {
        __nv_bfloat16* Khs = St + (size_t)s * FA_STAGE_ELEMS;
        __nv_bfloat16* Kls = Khs + FBN * FSTR;
        __nv_bfloat16* Vhs = Kls + FBN * FSTR;
        __nv_bfloat16* Vls = Vhs + FBN * FSTR;
        size_t base = head + (size_t)(kt * FBN) * HN;
#pragma unroll
        for (int j = 0; j < 4; j++) {
            int lin = tid + j * 256;
            int r = lin >> 4, c = (lin & 15) * 8;
            size_t g = base + (size_t)r * HN + c;
            int so = r * FSTR + c;
            cp16(&Khs[so], Khg + g);
            cp16(&Kls[so], Klg + g);
            cp16(&Vhs[so], Vhg + g);
            cp16(&Vls[so], Vlg + g);
        }
    };

#pragma unroll
    for (int j = 0; j < 8; j++) {
        int lin = tid + j * 256;
        int r = lin >> 4, c = (lin & 15) * 8;
        size_t g = head + (size_t)(row0 + r) * HN + c;
        cp16(&Qh[r * FSTR + c], Qhg + g);
        cp16(&Ql[r * FSTR + c], Qlg + g);
    }
    prefetch(0, 0);
    cp_commit();

    float oacc[16][4];
#pragma unroll
    for (int t = 0; t < 16; t++)
#pragma unroll
        for (int e = 0; e < 4; e++) oacc[t][e] = 0.f;
    float m_i[2] = {-1e30f, -1e30f};
    float l_i[2] = {0.f, 0.f};

    const int a_row = warp * 16 + (lane & 15);
    const int a_kh  = (lane >> 4) * 8;
    const int b_r   = (lane >> 4) * 8 + (lane & 7);
    const int b_kh  = ((lane >> 3) & 1) * 8;
    const int v_row = ((lane >> 3) & 1) * 8 + (lane & 7);
    const int v_col = (lane >> 4) * 8;
    const int gr    = lane >> 2;
    const int gc    = (lane & 3) * 2;
    const int wrow_last = row0 + warp * 16 + 15;

    const int nkt = (row0 + FBM) / FBN;
#pragma unroll 1
    for (int kt = 0; kt < nkt; kt++) {
        const int kr0 = kt * FBN;
        const int s = kt & 1;

        if (kt + 1 < nkt) {
            prefetch(kt + 1, (kt + 1) & 1);
            cp_commit();
            cp_wait<1>();
        } else {
            cp_wait<0>();
        }
        __syncthreads();

        if (kr0 <= wrow_last) {
            __nv_bfloat16* Khs = St + (size_t)s * FA_STAGE_ELEMS;
            __nv_bfloat16* Kls = Khs + FBN * FSTR;
            __nv_bfloat16* Vhs = Kls + FBN * FSTR;
            __nv_bfloat16* Vls = Vhs + FBN * FSTR;

            float sacc[8][4];
#pragma unroll
            for (int t = 0; t < 8; t++)
#pragma unroll
                for (int e = 0; e < 4; e++) sacc[t][e] = 0.f;

#pragma unroll
            for (int kk = 0; kk < 8; kk++) {
                uint32_t aH[4], aL[4];
                ldsm_x4(aH[0], aH[1], aH[2], aH[3],
                        smem_u32(&Qh[a_row * FSTR + kk * 16 + a_kh]));
                ldsm_x4(aL[0], aL[1], aL[2], aL[3],
                        smem_u32(&Ql[a_row * FSTR + kk * 16 + a_kh]));
#pragma unroll
                for (int nt2 = 0; nt2 < 4; nt2++) {
                    uint32_t bh[4], bl[4];
                    ldsm_x4(bh[0], bh[1], bh[2], bh[3],
                            smem_u32(&Khs[(nt2 * 16 + b_r) * FSTR + kk * 16 + b_kh]));
                    ldsm_x4(bl[0], bl[1], bl[2], bl[3],
                            smem_u32(&Kls[(nt2 * 16 + b_r) * FSTR + kk * 16 + b_kh]));
                    mma_bf16(sacc[nt2 * 2], aH, bh);
                    mma_bf16(sacc[nt2 * 2], aH, bl);
                    mma_bf16(sacc[nt2 * 2], aL, bh);
                    mma_bf16(sacc[nt2 * 2 + 1], aH, bh + 2);
                    mma_bf16(sacc[nt2 * 2 + 1], aH, bl + 2);
                    mma_bf16(sacc[nt2 * 2 + 1], aL, bh + 2);
                }
            }

            if (kr0 + FBN - 1 > row0 + warp * 16) {
                int grow0 = row0 + warp * 16 + gr;
#pragma unroll
                for (int t = 0; t < 8; t++) {
                    int colb = kr0 + t * 8 + gc;
                    if (colb     > grow0)     sacc[t][0] = -1e30f;
                    if (colb + 1 > grow0)     sacc[t][1] = -1e30f;
                    if (colb     > grow0 + 8) sacc[t][2] = -1e30f;
                    if (colb + 1 > grow0 + 8) sacc[t][3] = -1e30f;
                }
            }

            float mx0 = -1e30f, mx1 = -1e30f;
#pragma unroll
            for (int t = 0; t < 8; t++) {
                mx0 = fmaxf(mx0, fmaxf(sacc[t][0], sacc[t][1]));
                mx1 = fmaxf(mx1, fmaxf(sacc[t][2], sacc[t][3]));
            }
            mx0 = fmaxf(mx0, __shfl_xor_sync(0xffffffffu, mx0, 1));
            mx0 = fmaxf(mx0, __shfl_xor_sync(0xffffffffu, mx0, 2));
            mx1 = fmaxf(mx1, __shfl_xor_sync(0xffffffffu, mx1, 1));
            mx1 = fmaxf(mx1, __shfl_xor_sync(0xffffffffu, mx1, 2));
            float mn0 = fmaxf(m_i[0], mx0);
            float mn1 = fmaxf(m_i[1], mx1);
            float corr0 = __expf(m_i[0] - mn0);
            float corr1 = __expf(m_i[1] - mn1);

            uint32_t aPh[4][4], aPl[4][4];
            float rs0 = 0.f, rs1 = 0.f;
#pragma unroll
            for (int t = 0; t < 8; t++) {
                float p00 = __expf(sacc[t][0] - mn0);
                float p01 = __expf(sacc[t][1] - mn0);
                float p10 = __expf(sacc[t][2] - mn1);
                float p11 = __expf(sacc[t][3] - mn1);
                rs0 += p00 + p01;
                rs1 += p10 + p11;
                int kc = t >> 1, half = (t & 1) * 2;
                float h00 = __bfloat162float(__float2bfloat16_rn(p00));
                float h01 = __bfloat162float(__float2bfloat16_rn(p01));
                float h10 = __bfloat162float(__float2bfloat16_rn(p10));
                float h11 = __bfloat162float(__float2bfloat16_rn(p11));
                aPh[kc][half]     = pack_bf2(h00, h01);
                aPh[kc][half + 1] = pack_bf2(h10, h11);
                aPl[kc][half]     = pack_bf2(p00 - h00, p01 - h01);
                aPl[kc][half + 1] = pack_bf2(p10 - h10, p11 - h11);
            }
            rs0 += __shfl_xor_sync(0xffffffffu, rs0, 1);
            rs0 += __shfl_xor_sync(0xffffffffu, rs0, 2);
            rs1 += __shfl_xor_sync(0xffffffffu, rs1, 1);
            rs1 += __shfl_xor_sync(0xffffffffu, rs1, 2);
            l_i[0] = l_i[0] * corr0 + rs0;  m_i[0] = mn0;
            l_i[1] = l_i[1] * corr1 + rs1;  m_i[1] = mn1;

#pragma unroll
            for (int t = 0; t < 16; t++) {
                oacc[t][0] *= corr0; oacc[t][1] *= corr0;
                oacc[t][2] *= corr1; oacc[t][3] *= corr1;
            }

#pragma unroll
            for (int kc = 0; kc < 4; kc++) {
#pragma unroll
                for (int nt2 = 0; nt2 < 8; nt2++) {
                    uint32_t bh[4], bl[4];
                    ldsm_x4_t(bh[0], bh[1], bh[2], bh[3],
                              smem_u32(&Vhs[(kc * 16 + v_row) * FSTR + nt2 * 16 + v_col]));
                    ldsm_x4_t(bl[0], bl[1], bl[2], bl[3],
                              smem_u32(&Vls[(kc * 16 + v_row) * FSTR + nt2 * 16 + v_col]));
                    mma_bf16(oacc[nt2 * 2], aPh[kc], bh);
                    mma_bf16(oacc[nt2 * 2], aPh[kc], bl);
                    mma_bf16(oacc[nt2 * 2], aPl[kc], bh);
                    mma_bf16(oacc[nt2 * 2 + 1], aPh[kc], bh + 2);
                    mma_bf16(oacc[nt2 * 2 + 1], aPh[kc], bl + 2);
                    mma_bf16(oacc[nt2 * 2 + 1], aPl[kc], bh + 2);
                }
            }
        }

        __syncthreads();
    }

    {
        float inv0 = 1.0f / l_i[0];
        float inv1 = 1.0f / l_i[1];
        int s0 = row0 + warp * 16 + gr;
        size_t o0 = ((size_t)s0 * BATCH + b) * HID + n * HN;
        size_t o1 = ((size_t)(s0 + 8) * BATCH + b) * HID + n * HN;
#pragma unroll
        for (int t = 0; t < 16; t++) {
            int col = t * 8 + gc;
            float a0 = oacc[t][0] * inv0, a1 = oacc[t][1] * inv0;
            float b0 = oacc[t][2] * inv1, b1 = oacc[t][3] * inv1;
            __nv_bfloat16 ha0 = __float2bfloat16_rn(a0);
            __nv_bfloat16 ha1 = __float2bfloat16_rn(a1);
            __nv_bfloat16 hb0 = __float2bfloat16_rn(b0);
            __nv_bfloat16 hb1 = __float2bfloat16_rn(b1);
            __nv_bfloat162 t2;
            t2.x = ha0; t2.y = ha1; *(__nv_bfloat162*)&Ch[o0 + col] = t2;
            t2.x = hb0; t2.y = hb1; *(__nv_bfloat162*)&Ch[o1 + col] = t2;
            t2.x = __float2bfloat16_rn(a0 - __bfloat162float(ha0));
            t2.y = __float2bfloat16_rn(a1 - __bfloat162float(ha1));
            *(__nv_bfloat162*)&Cl[o0 + col] = t2;
            t2.x = __float2bfloat16_rn(b0 - __bfloat162float(hb0));
            t2.y = __float2bfloat16_rn(b1 - __bfloat162float(hb1));
            *(__nv_bfloat162*)&Cl[o1 + col] = t2;
        }
    }
}

// ---------------------------------------------------------------------------
// Launch
// ---------------------------------------------------------------------------
extern "C" void kernel_launch(void* const* d_in, const int* in_sizes, int n_in,
                              void* d_out, int out_size)
{
    const float* hidden  = (const float*)d_in[0];
    // d_in[1] = attention_mask (causal; handled analytically)
    const float* w_qkv   = (const float*)d_in[2];
    const float* b_qkv   = (const float*)d_in[3];
    const float* w_dense = (const float*)d_in[4];
    const float* b_dense = (const float*)d_in[5];
    float* out = (float*)d_out;

    __nv_bfloat16 *qh, *ql, *kh, *kl, *vh, *vl;
    __nv_bfloat16 *hh, *hl, *wqh, *wql, *wdh, *wdl, *ch, *cl;
    float2* rottab;
    cudaGetSymbolAddress((void**)&qh,  g_qh);
    cudaGetSymbolAddress((void**)&ql,  g_ql);
    cudaGetSymbolAddress((void**)&kh,  g_kh);
    cudaGetSymbolAddress((void**)&kl,  g_kl);
    cudaGetSymbolAddress((void**)&vh,  g_vh);
    cudaGetSymbolAddress((void**)&vl,  g_vl);
    cudaGetSymbolAddress((void**)&hh,  g_hh);
    cudaGetSymbolAddress((void**)&hl,  g_hl);
    cudaGetSymbolAddress((void**)&wqh, g_wqh);
    cudaGetSymbolAddress((void**)&wql, g_wql);
    cudaGetSymbolAddress((void**)&wdh, g_wdh);
    cudaGetSymbolAddress((void**)&wdl, g_wdl);
    cudaGetSymbolAddress((void**)&ch,  g_ch);
    cudaGetSymbolAddress((void**)&cl,  g_cl);
    cudaGetSymbolAddress((void**)&rottab, g_rottab);

    cudaFuncSetAttribute(bf16x3_gemm_nt<0>,
                         cudaFuncAttributeMaxDynamicSharedMemorySize, GEMM_SMEM_BYTES);
    cudaFuncSetAttribute(bf16x3_gemm_nt<1>,
                         cudaFuncAttributeMaxDynamicSharedMemorySize, GEMM_SMEM_BYTES);
    cudaFuncSetAttribute(flash_hmma_kernel,
                         cudaFuncAttributeMaxDynamicSharedMemorySize, FA_SMEM_BYTES);

    // 0) rotary table + pre-split activations & weights
    rottab_kernel<<<(S_LEN * 64) / 256, 256>>>(rottab);
    split_f32_bf16x2<<<(M_ROWS * HID) / 1024, 256>>>(hidden, hh, hl);
    split_f32_bf16x2<<<(QKV_N * HID) / 1024, 256>>>(w_qkv, wqh, wql);
    split_f32_bf16x2<<<(HID * HID) / 1024, 256>>>(w_dense, wdh, wdl);

    // 1) QKV projection with fused rotary + hi/lo split epilogue
    bf16x3_gemm_nt<1><<<dim3(QKV_N / TBN, M_ROWS / TBM), 256, GEMM_SMEM_BYTES>>>(
        hh, hl, wqh, wql, b_qkv, nullptr, rottab,
        qh, ql, kh, kl, vh, vl, M_ROWS, QKV_N, HID);

    // 2) Causal flash attention -> ctx hi/lo planes
    flash_hmma_kernel<<<dim3(S_LEN / FBM, NP, BATCH), 256, FA_SMEM_BYTES>>>(
        qh, ql, kh, kl, vh, vl, ch, cl);

    // 3) Dense projection (plain epilogue)
    bf16x3_gemm_nt<0><<<dim3(HID / TBN, M_ROWS / TBM), 256, GEMM_SMEM_BYTES>>>(
        ch, cl, wdh, wdl, b_dense, out, nullptr,
        nullptr, nullptr, nullptr, nullptr, nullptr, nullptr, M_ROWS, HID, HID);
}

// round 15
// speedup vs baseline: 1.6458x; 1.2915x over previous
#include <cuda_runtime.h>
#include <cuda_bf16.h>
#include <cuda_fp16.h>
#include <math.h>
#include <stdint.h>

// Problem constants
#define S_LEN 2048
#define BATCH 2
#define HID   2048
#define NP    16
#define HN    128
#define M_ROWS (S_LEN*BATCH)     // 4096
#define QKV_N  (3*HID)           // 6144
#define HEAD_ELEMS ((size_t)BATCH * NP * S_LEN * HN)   // 8388608

// ---------------------------------------------------------------------------
// Scratch (device globals; no runtime allocation allowed)
// ---------------------------------------------------------------------------
__device__ __nv_bfloat16 g_qh[HEAD_ELEMS], g_ql[HEAD_ELEMS];    // [b][n][s][d]
__device__ __nv_bfloat16 g_kh[HEAD_ELEMS], g_kl[HEAD_ELEMS];
__device__ __nv_bfloat16 g_vh[HEAD_ELEMS], g_vl[HEAD_ELEMS];
__device__ __half g_h16[(size_t)M_ROWS * HID];                  // hidden (hi fp16)
__device__ __half g_wqh16[(size_t)QKV_N * HID], g_wql16[(size_t)QKV_N * HID];
__device__ __half g_wdh16[(size_t)HID * HID],  g_wdl16[(size_t)HID * HID];
__device__ __half g_c16[(size_t)M_ROWS * HID];                  // ctx (hi fp16)
__device__ float2 g_rottab[S_LEN * 64];                         // (cos,sin)[s][i]

// ---------------------------------------------------------------------------
// PTX helpers
// ---------------------------------------------------------------------------
__device__ __forceinline__ uint32_t smem_u32(const void* p) {
    return (uint32_t)__cvta_generic_to_shared(p);
}
__device__ __forceinline__ void ldsm_x4(uint32_t& r0, uint32_t& r1,
                                        uint32_t& r2, uint32_t& r3, uint32_t addr) {
    asm volatile("ldmatrix.sync.aligned.m8n8.x4.shared.b16 {%0,%1,%2,%3}, [%4];"
        : "=r"(r0), "=r"(r1), "=r"(r2), "=r"(r3) : "r"(addr));
}
__device__ __forceinline__ void ldsm_x4_t(uint32_t& r0, uint32_t& r1,
                                          uint32_t& r2, uint32_t& r3, uint32_t addr) {
    asm volatile("ldmatrix.sync.aligned.m8n8.x4.trans.shared.b16 {%0,%1,%2,%3}, [%4];"
        : "=r"(r0), "=r"(r1), "=r"(r2), "=r"(r3) : "r"(addr));
}
__device__ __forceinline__ void mma_bf16(float* d, const uint32_t* a, const uint32_t* b) {
    asm volatile("mma.sync.aligned.m16n8k16.row.col.f32.bf16.bf16.f32 "
        "{%0,%1,%2,%3}, {%4,%5,%6,%7}, {%8,%9}, {%0,%1,%2,%3};"
        : "+f"(d[0]), "+f"(d[1]), "+f"(d[2]), "+f"(d[3])
        : "r"(a[0]), "r"(a[1]), "r"(a[2]), "r"(a[3]), "r"(b[0]), "r"(b[1]));
}
__device__ __forceinline__ void mma_f16(float* d, const uint32_t* a, const uint32_t* b) {
    asm volatile("mma.sync.aligned.m16n8k16.row.col.f32.f16.f16.f32 "
        "{%0,%1,%2,%3}, {%4,%5,%6,%7}, {%8,%9}, {%0,%1,%2,%3};"
        : "+f"(d[0]), "+f"(d[1]), "+f"(d[2]), "+f"(d[3])
        : "r"(a[0]), "r"(a[1]), "r"(a[2]), "r"(a[3]), "r"(b[0]), "r"(b[1]));
}
__device__ __forceinline__ uint32_t pack_bf2(float a, float b) {
    __nv_bfloat162 t;
    t.x = __float2bfloat16_rn(a);
    t.y = __float2bfloat16_rn(b);
    return *(uint32_t*)&t;
}
__device__ __forceinline__ void cp16(void* sdst, const void* gsrc) {
    asm volatile("cp.async.cg.shared.global [%0], [%1], 16;\n"
        :: "r"(smem_u32(sdst)), "l"(gsrc));
}
__device__ __forceinline__ void cp_commit() {
    asm volatile("cp.async.commit_group;\n");
}
template <int N>
__device__ __forceinline__ void cp_wait() {
    asm volatile("cp.async.wait_group %0;\n" :: "n"(N));
}
__device__ __forceinline__ void split_store(__nv_bfloat16* H, __nv_bfloat16* L,
                                            size_t idx, float v) {
    __nv_bfloat16 h = __float2bfloat16_rn(v);
    H[idx] = h;
    L[idx] = __float2bfloat16_rn(v - __bfloat162float(h));
}

// ---------------------------------------------------------------------------
// rotary (cos,sin) table: [s][i], i in [0,64)
// ---------------------------------------------------------------------------
__global__ __launch_bounds__(256) void rottab_kernel(float2* __restrict__ tab) {
    int idx = blockIdx.x * 256 + threadIdx.x;      // 131072 total
    int s = idx >> 6, i = idx & 63;
    float expo = (float)(2 * i) / (float)HN;
    float freq = powf(1e-4f, expo);
    float ang  = (float)s * freq;
    float sn, cs;
    sincosf(ang, &sn, &cs);
    tab[idx] = make_float2(cs, sn);
}

// ---------------------------------------------------------------------------
// fp32 -> fp16 hi only (activations)
// ---------------------------------------------------------------------------
__global__ __launch_bounds__(256) void cvt_f32_f16(
    const float* __restrict__ src, __half* __restrict__ dst)
{
    size_t i = ((size_t)blockIdx.x * 256 + threadIdx.x) * 4;
    float4 v = *(const float4*)(src + i);
    __half2 t;
    t.x = __float2half_rn(v.x); t.y = __float2half_rn(v.y);
    *(__half2*)(dst + i) = t;
    t.x = __float2half_rn(v.z); t.y = __float2half_rn(v.w);
    *(__half2*)(dst + i + 2) = t;
}

// ---------------------------------------------------------------------------
// fp32 -> fp16 hi/lo split (weights)
// ---------------------------------------------------------------------------
__global__ __launch_bounds__(256) void split_f32_f16x2(
    const float* __restrict__ src,
    __half* __restrict__ hi, __half* __restrict__ lo)
{
    size_t i = ((size_t)blockIdx.x * 256 + threadIdx.x) * 4;
    float4 v = *(const float4*)(src + i);
    __half h0 = __float2half_rn(v.x);
    __half h1 = __float2half_rn(v.y);
    __half h2 = __float2half_rn(v.z);
    __half h3 = __float2half_rn(v.w);
    __half2 t;
    t.x = h0; t.y = h1; *(__half2*)(hi + i)     = t;
    t.x = h2; t.y = h3; *(__half2*)(hi + i + 2) = t;
    t.x = __float2half_rn(v.x - __half2float(h0));
    t.y = __float2half_rn(v.y - __half2float(h1));
    *(__half2*)(lo + i) = t;
    t.x = __float2half_rn(v.z - __half2float(h2));
    t.y = __float2half_rn(v.w - __half2float(h3));
    *(__half2*)(lo + i + 2) = t;
}

// ---------------------------------------------------------------------------
// fp16x2 GEMM (NT): C = A16 * (Bh+Bl)^T + bias   (2 mma products)
// 3-stage cp.async pipeline, ONE sync per k-tile, packed XOR-swizzled smem,
// 2 CTAs/SM. BM=BN=128, BK=32, 256 threads (8 warps 4x2), warp tile 32x64.
// FUSE=1: QKV epilogue (rotary + bf16 hi/lo split to [b][n][s][d] planes).
// ---------------------------------------------------------------------------
#define TBM 128
#define TBN 128
#define TBK 32
#define NSTAGE 3
#define PLANE_E (128*32)                     // 4096 halves per plane
#define STAGE_E (3*PLANE_E)                  // A|Bh|Bl = 12288 halves = 24 KB
#define GEMM_SMEM_BYTES (NSTAGE*STAGE_E*2)   // 73728 B (x2 CTAs = 144 KB/SM)
#define EPI_STR 136                          // fp32 epilogue smem stride

__device__ __forceinline__ int swz_off(int row, int chunk) {
    return row * 32 + ((chunk ^ ((row >> 1) & 3)) << 3);
}

template <int FUSE>
__global__ __launch_bounds__(256, 2) void f16x2_gemm_nt(
    const __half* __restrict__ A16,
    const __half* __restrict__ Bh, const __half* __restrict__ Bl,
    const float* __restrict__ bias, float* __restrict__ C,
    const float2* __restrict__ rottab,
    __nv_bfloat16* __restrict__ Qh, __nv_bfloat16* __restrict__ Ql,
    __nv_bfloat16* __restrict__ Kh, __nv_bfloat16* __restrict__ Kl,
    __nv_bfloat16* __restrict__ Vh, __nv_bfloat16* __restrict__ Vl,
    int M, int N, int K)
{
    extern __shared__ __half smg[];

    const int tid  = threadIdx.x;
    const int bx   = blockIdx.x, by = blockIdx.y;
    const int warp = tid >> 5, lane = tid & 31;
    const int wr   = warp & 3;
    const int wc   = warp >> 2;

    auto prefetch = [&](int kt, int s) {
        __half* st = smg + (size_t)s * STAGE_E;
        const size_t kof = (size_t)kt * TBK;
#pragma unroll
        for (int j = 0; j < 2; j++) {
            int lin = tid + j * 256;          // 512 chunks per plane
            int r = lin >> 2, c = lin & 3;
            int so = swz_off(r, c);
            size_t ga = (size_t)(by * TBM + r) * K + kof + c * 8;
            size_t gb = (size_t)(bx * TBN + r) * K + kof + c * 8;
            cp16(st + so,               A16 + ga);
            cp16(st + PLANE_E + so,     Bh + gb);
            cp16(st + 2 * PLANE_E + so, Bl + gb);
        }
    };

    float acc[2][8][4];
#pragma unroll
    for (int mi = 0; mi < 2; mi++)
#pragma unroll
        for (int ni = 0; ni < 8; ni++)
#pragma unroll
            for (int e = 0; e < 4; e++) acc[mi][ni][e] = 0.f;

    const int a_row = wr * 32 + (lane & 15);
    const int a_kc  = lane >> 4;
    const int bg    = lane >> 3;
    const int b_row = wc * 64 + ((bg >> 1) << 3) + (lane & 7);
    const int b_kc  = bg & 1;

    auto compute = [&](int s) {
        const __half* A0 = smg + (size_t)s * STAGE_E;
        const __half* B0 = A0 + PLANE_E;
        const __half* B1 = A0 + 2 * PLANE_E;
#pragma unroll
        for (int kk = 0; kk < 2; kk++) {
            uint32_t af[2][4];
#pragma unroll
            for (int mi = 0; mi < 2; mi++) {
                int ra = a_row + mi * 16;
                int off = swz_off(ra, kk * 2 + a_kc);
                ldsm_x4(af[mi][0], af[mi][1], af[mi][2], af[mi][3],
                        smem_u32(A0 + off));
            }
#pragma unroll
            for (int np = 0; np < 4; np++) {
                int rb = b_row + np * 16;
                int off = swz_off(rb, kk * 2 + b_kc);
                uint32_t b0[4], b1[4];
                ldsm_x4(b0[0], b0[1], b0[2], b0[3], smem_u32(B0 + off));
                ldsm_x4(b1[0], b1[1], b1[2], b1[3], smem_u32(B1 + off));
#pragma unroll
                for (int mi = 0; mi < 2; mi++) {
                    mma_f16(acc[mi][np * 2],     af[mi], b0);        // A*Bh
                    mma_f16(acc[mi][np * 2],     af[mi], b1);        // A*Bl
                    mma_f16(acc[mi][np * 2 + 1], af[mi], b0 + 2);
                    mma_f16(acc[mi][np * 2 + 1], af[mi], b1 + 2);
                }
            }
        }
    };

    const int nt = K / TBK;
    prefetch(0, 0); cp_commit();
    prefetch(1, 1); cp_commit();
#pragma unroll 1
    for (int kt = 0; kt < nt; kt++) {
        cp_wait<1>();
        __syncthreads();
        if (kt + 2 < nt) prefetch(kt + 2, (kt + 2) % NSTAGE);
        cp_commit();
        compute(kt % NSTAGE);
    }

    const int gr = lane >> 2, gc = (lane & 3) * 2;

    if (FUSE == 0) {
        // ---- plain epilogue: bias + fp32 C ----
#pragma unroll
        for (int mi = 0; mi < 2; mi++) {
            int row = by * TBM + wr * 32 + mi * 16 + gr;
#pragma unroll
            for (int ni = 0; ni < 8; ni++) {
                int col = bx * TBN + wc * 64 + ni * 8 + gc;
                float b0 = bias[col], b1 = bias[col + 1];
                float2 v0, v1;
                v0.x = acc[mi][ni][0] + b0; v0.y = acc[mi][ni][1] + b1;
                v1.x = acc[mi][ni][2] + b0; v1.y = acc[mi][ni][3] + b1;
                *(float2*)&C[(size_t)row * N + col] = v0;
                *(float2*)&C[(size_t)(row + 8) * N + col] = v1;
            }
        }
    } else {
        // ---- fused QKV epilogue: stage tile (+bias) in smem fp32 ----
        __syncthreads();    // all compute + smem reads done; reuse smem
        float* sc = (float*)smg;            // [128][EPI_STR] = 69632 B
#pragma unroll
        for (int mi = 0; mi < 2; mi++) {
            int row = wr * 32 + mi * 16 + gr;
#pragma unroll
            for (int ni = 0; ni < 8; ni++) {
                int col = wc * 64 + ni * 8 + gc;
                int gcol = bx * TBN + col;
                float b0 = bias[gcol], b1 = bias[gcol + 1];
                sc[row * EPI_STR + col]           = acc[mi][ni][0] + b0;
                sc[row * EPI_STR + col + 1]       = acc[mi][ni][1] + b1;
                sc[(row + 8) * EPI_STR + col]     = acc[mi][ni][2] + b0;
                sc[(row + 8) * EPI_STR + col + 1] = acc[mi][ni][3] + b1;
            }
        }
        __syncthreads();

        const int type = bx % 3;            // 0=q, 1=k, 2=v
        const int n    = bx / 3;
        const float qscale = 0.0883883476483184f;   // 1/sqrt(128)

        if (type < 2) {
            __nv_bfloat16* H = (type == 0) ? Qh : Kh;
            __nv_bfloat16* L = (type == 0) ? Ql : Kl;
#pragma unroll 4
            for (int j = 0; j < 32; j++) {
                int p = tid + j * 256;      // 0..8191
                int r = p >> 6;
                int i = p & 63;
                int grow = by * TBM + r;    // s*BATCH + b
                int s = grow >> 1, bb = grow & 1;
                float Lv = sc[r * EPI_STR + i];
                float Rv = sc[r * EPI_STR + i + 64];
                float2 cssn = rottab[s * 64 + i];
                float x0 = cssn.x * Lv - cssn.y * Rv;
                float x1 = cssn.y * Lv + cssn.x * Rv;
                if (type == 0) { x0 *= qscale; x1 *= qscale; }
                size_t dst = (((size_t)bb * NP + n) * S_LEN + s) * HN;
                split_store(H, L, dst + i,      x0);
                split_store(H, L, dst + i + 64, x1);
            }
        } else {
#pragma unroll 4
            for (int j = 0; j < 64; j++) {
                int p = tid + j * 256;      // 0..16383
                int r = p >> 7;
                int c = p & 127;
                int grow = by * TBM + r;
                int s = grow >> 1, bb = grow & 1;
                float x = sc[r * EPI_STR + c];
                size_t dst = (((size_t)bb * NP + n) * S_LEN + s) * HN + c;
                split_store(Vh, Vl, dst, x);
            }
        }
    }
}

// ---------------------------------------------------------------------------
// HMMA flash attention (bf16x3), cp.async double-buffered; ctx out fp16.
// ---------------------------------------------------------------------------
#define FBM 128
#define FBN 64
#define FSTR 136
#define FA_STAGE_ELEMS (4*FBN*FSTR)
#define FA_SMEM_BYTES ((2*FBM*FSTR + 2*FA_STAGE_ELEMS) * 2)   // 208896

__global__ __launch_bounds__(256, 1) void flash_hmma_kernel(
    const __nv_bfloat16* __restrict__ Qhg, const __nv_bfloat16* __restrict__ Qlg,
    const __nv_bfloat16* __restrict__ Khg, const __nv_bfloat16* __restrict__ Klg,
    const __nv_bfloat16* __restrict__ Vhg, const __nv_bfloat16* __restrict__ Vlg,
    __half* __restrict__ C16)
{
    extern __shared__ __nv_bfloat16 fsm[];
    __nv_bfloat16* Qh = fsm;
    __nv_bfloat16* Ql = Qh + FBM * FSTR;
    __nv_bfloat16* St = Ql + FBM * FSTR;

    const int qt = gridDim.x - 1 - blockIdx.x;
    const int n  = blockIdx.y;
    const int b  = blockIdx.z;
    const int tid  = threadIdx.x;
    const int warp = tid >> 5, lane = tid & 31;

    const size_t head = ((size_t)b * NP + n) * (size_t)S_LEN * HN;
    const int row0 = qt * FBM;

    auto prefetch = [&](int kt, int s) {
        __nv_bfloat16* Khs = St + (size_t)s * FA_STAGE_ELEMS;
        __nv_bfloat16* Kls = Khs + FBN * FSTR;
        __nv_bfloat16* Vhs = Kls + FBN * FSTR;
        __nv_bfloat16* Vls = Vhs + FBN * FSTR;
        size_t base = head + (size_t)(kt * FBN) * HN;
#pragma unroll
        for (int j = 0; j < 4; j++) {
            int lin = tid + j * 256;
            int r = lin >> 4, c = (lin & 15) * 8;
            size_t g = base + (size_t)r * HN + c;
            int so = r * FSTR + c;
            cp16(&Khs[so], Khg + g);
            cp16(&Kls[so], Klg + g);
            cp16(&Vhs[so], Vhg + g);
            cp16(&Vls[so], Vlg + g);
        }
    };

#pragma unroll
    for (int j = 0; j < 8; j++) {
        int lin = tid + j * 256;
        int r = lin >> 4, c = (lin & 15) * 8;
        size_t g = head + (size_t)(row0 + r) * HN + c;
        cp16(&Qh[r * FSTR + c], Qhg + g);
        cp16(&Ql[r * FSTR + c], Qlg + g);
    }
    prefetch(0, 0);
    cp_commit();

    float oacc[16][4];
#pragma unroll
    for (int t = 0; t < 16; t++)
#pragma unroll
        for (int e = 0; e < 4; e++) oacc[t][e] = 0.f;
    float m_i[2] = {-1e30f, -1e30f};
    float l_i[2] = {0.f, 0.f};

    const int a_row = warp * 16 + (lane & 15);
    const int a_kh  = (lane >> 4) * 8;
    const int b_r   = (lane >> 4) * 8 + (lane & 7);
    const int b_kh  = ((lane >> 3) & 1) * 8;
    const int v_row = ((lane >> 3) & 1) * 8 + (lane & 7);
    const int v_col = (lane >> 4) * 8;
    const int gr    = lane >> 2;
    const int gc    = (lane & 3) * 2;
    const int wrow_last = row0 + warp * 16 + 15;

    const int nkt = (row0 + FBM) / FBN;
#pragma unroll 1
    for (int kt = 0; kt < nkt; kt++) {
        const int kr0 = kt * FBN;
        const int s = kt & 1;

        if (kt + 1 < nkt) {
            prefetch(kt + 1, (kt + 1) & 1);
            cp_commit();
            cp_wait<1>();
        } else {
            cp_wait<0>();
        }
        __syncthreads();

        if (kr0 <= wrow_last) {
            __nv_bfloat16* Khs = St + (size_t)s * FA_STAGE_ELEMS;
            __nv_bfloat16* Kls = Khs + FBN * FSTR;
            __nv_bfloat16* Vhs = Kls + FBN * FSTR;
            __nv_bfloat16* Vls = Vhs + FBN * FSTR;

            float sacc[8][4];
#pragma unroll
            for (int t = 0; t < 8; t++)
#pragma unroll
                for (int e = 0; e < 4; e++) sacc[t][e] = 0.f;

#pragma unroll
            for (int kk = 0; kk < 8; kk++) {
                uint32_t aH[4], aL[4];
                ldsm_x4(aH[0], aH[1], aH[2], aH[3],
                        smem_u32(&Qh[a_row * FSTR + kk * 16 + a_kh]));
                ldsm_x4(aL[0], aL[1], aL[2], aL[3],
                        smem_u32(&Ql[a_row * FSTR + kk * 16 + a_kh]));
#pragma unroll
                for (int nt2 = 0; nt2 < 4; nt2++) {
                    uint32_t bh[4], bl[4];
                    ldsm_x4(bh[0], bh[1], bh[2], bh[3],
                            smem_u32(&Khs[(nt2 * 16 + b_r) * FSTR + kk * 16 + b_kh]));
                    ldsm_x4(bl[0], bl[1], bl[2], bl[3],
                            smem_u32(&Kls[(nt2 * 16 + b_r) * FSTR + kk * 16 + b_kh]));
                    mma_bf16(sacc[nt2 * 2], aH, bh);
                    mma_bf16(sacc[nt2 * 2], aH, bl);
                    mma_bf16(sacc[nt2 * 2], aL, bh);
                    mma_bf16(sacc[nt2 * 2 + 1], aH, bh + 2);
                    mma_bf16(sacc[nt2 * 2 + 1], aH, bl + 2);
                    mma_bf16(sacc[nt2 * 2 + 1], aL, bh + 2);
                }
            }

            if (kr0 + FBN - 1 > row0 + warp * 16) {
                int grow0 = row0 + warp * 16 + gr;
#pragma unroll
                for (int t = 0; t < 8; t++) {
                    int colb = kr0 + t * 8 + gc;
                    if (colb     > grow0)     sacc[t][0] = -1e30f;
                    if (colb + 1 > grow0)     sacc[t][1] = -1e30f;
                    if (colb     > grow0 + 8) sacc[t][2] = -1e30f;
                    if (colb + 1 > grow0 + 8) sacc[t][3] = -1e30f;
                }
            }

            float mx0 = -1e30f, mx1 = -1e30f;
#pragma unroll
            for (int t = 0; t < 8; t++) {
                mx0 = fmaxf(mx0, fmaxf(sacc[t][0], sacc[t][1]));
                mx1 = fmaxf(mx1, fmaxf(sacc[t][2], sacc[t][3]));
            }
            mx0 = fmaxf(mx0, __shfl_xor_sync(0xffffffffu, mx0, 1));
            mx0 = fmaxf(mx0, __shfl_xor_sync(0xffffffffu, mx0, 2));
            mx1 = fmaxf(mx1, __shfl_xor_sync(0xffffffffu, mx1, 1));
            mx1 = fmaxf(mx1, __shfl_xor_sync(0xffffffffu, mx1, 2));
            float mn0 = fmaxf(m_i[0], mx0);
            float mn1 = fmaxf(m_i[1], mx1);
            float corr0 = __expf(m_i[0] - mn0);
            float corr1 = __expf(m_i[1] - mn1);

            uint32_t aPh[4][4], aPl[4][4];
            float rs0 = 0.f, rs1 = 0.f;
#pragma unroll
            for (int t = 0; t < 8; t++) {
                float p00 = __expf(sacc[t][0] - mn0);
                float p01 = __expf(sacc[t][1] - mn0);
                float p10 = __expf(sacc[t][2] - mn1);
                float p11 = __expf(sacc[t][3] - mn1);
                rs0 += p00 + p01;
                rs1 += p10 + p11;
                int kc = t >> 1, half = (t & 1) * 2;
                float h00 = __bfloat162float(__float2bfloat16_rn(p00));
                float h01 = __bfloat162float(__float2bfloat16_rn(p01));
                float h10 = __bfloat162float(__float2bfloat16_rn(p10));
                float h11 = __bfloat162float(__float2bfloat16_rn(p11));
                aPh[kc][half]     = pack_bf2(h00, h01);
                aPh[kc][half + 1] = pack_bf2(h10, h11);
                aPl[kc][half]     = pack_bf2(p00 - h00, p01 - h01);
                aPl[kc][half + 1] = pack_bf2(p10 - h10, p11 - h11);
            }
            rs0 += __shfl_xor_sync(0xffffffffu, rs0, 1);
            rs0 += __shfl_xor_sync(0xffffffffu, rs0, 2);
            rs1 += __shfl_xor_sync(0xffffffffu, rs1, 1);
            rs1 += __shfl_xor_sync(0xffffffffu, rs1, 2);
            l_i[0] = l_i[0] * corr0 + rs0;  m_i[0] = mn0;
            l_i[1] = l_i[1] * corr1 + rs1;  m_i[1] = mn1;

#pragma unroll
            for (int t = 0; t < 16; t++) {
                oacc[t][0] *= corr0; oacc[t][1] *= corr0;
                oacc[t][2] *= corr1; oacc[t][3] *= corr1;
            }

#pragma unroll
            for (int kc = 0; kc < 4; kc++) {
#pragma unroll
                for (int nt2 = 0; nt2 < 8; nt2++) {
                    uint32_t bh[4], bl[4];
                    ldsm_x4_t(bh[0], bh[1], bh[2], bh[3],
                              smem_u32(&Vhs[(kc * 16 + v_row) * FSTR + nt2 * 16 + v_col]));
                    ldsm_x4_t(bl[0], bl[1], bl[2], bl[3],
                              smem_u32(&Vls[(kc * 16 + v_row) * FSTR + nt2 * 16 + v_col]));
                    mma_bf16(oacc[nt2 * 2], aPh[kc], bh);
                    mma_bf16(oacc[nt2 * 2], aPh[kc], bl);
                    mma_bf16(oacc[nt2 * 2], aPl[kc], bh);
                    mma_bf16(oacc[nt2 * 2 + 1], aPh[kc], bh + 2);
                    mma_bf16(oacc[nt2 * 2 + 1], aPh[kc], bl + 2);
                    mma_bf16(oacc[nt2 * 2 + 1], aPl[kc], bh + 2);
                }
            }
        }

        __syncthreads();
    }

    {
        float inv0 = 1.0f / l_i[0];
        float inv1 = 1.0f / l_i[1];
        int s0 = row0 + warp * 16 + gr;
        size_t o0 = ((size_t)s0 * BATCH + b) * HID + n * HN;
        size_t o1 = ((size_t)(s0 + 8) * BATCH + b) * HID + n * HN;
#pragma unroll
        for (int t = 0; t < 16; t++) {
            int col = t * 8 + gc;
            __half2 t2;
            t2.x = __float2half_rn(oacc[t][0] * inv0);
            t2.y = __float2half_rn(oacc[t][1] * inv0);
            *(__half2*)&C16[o0 + col] = t2;
            t2.x = __float2half_rn(oacc[t][2] * inv1);
            t2.y = __float2half_rn(oacc[t][3] * inv1);
            *(__half2*)&C16[o1 + col] = t2;
        }
    }
}

// ---------------------------------------------------------------------------
// Launch
// ---------------------------------------------------------------------------
extern "C" void kernel_launch(void* const* d_in, const int* in_sizes, int n_in,
                              void* d_out, int out_size)
{
    const float* hidden  = (const float*)d_in[0];
    // d_in[1] = attention_mask (causal; handled analytically)
    const float* w_qkv   = (const float*)d_in[2];
    const float* b_qkv   = (const float*)d_in[3];
    const float* w_dense = (const float*)d_in[4];
    const float* b_dense = (const float*)d_in[5];
    float* out = (float*)d_out;

    __nv_bfloat16 *qh, *ql, *kh, *kl, *vh, *vl;
    __half *h16, *wqh16, *wql16, *wdh16, *wdl16, *c16;
    float2* rottab;
    cudaGetSymbolAddress((void**)&qh,  g_qh);
    cudaGetSymbolAddress((void**)&ql,  g_ql);
    cudaGetSymbolAddress((void**)&kh,  g_kh);
    cudaGetSymbolAddress((void**)&kl,  g_kl);
    cudaGetSymbolAddress((void**)&vh,  g_vh);
    cudaGetSymbolAddress((void**)&vl,  g_vl);
    cudaGetSymbolAddress((void**)&h16,   g_h16);
    cudaGetSymbolAddress((void**)&wqh16, g_wqh16);
    cudaGetSymbolAddress((void**)&wql16, g_wql16);
    cudaGetSymbolAddress((void**)&wdh16, g_wdh16);
    cudaGetSymbolAddress((void**)&wdl16, g_wdl16);
    cudaGetSymbolAddress((void**)&c16,   g_c16);
    cudaGetSymbolAddress((void**)&rottab, g_rottab);

    cudaFuncSetAttribute(f16x2_gemm_nt<0>,
                         cudaFuncAttributeMaxDynamicSharedMemorySize, GEMM_SMEM_BYTES);
    cudaFuncSetAttribute(f16x2_gemm_nt<1>,
                         cudaFuncAttributeMaxDynamicSharedMemorySize, GEMM_SMEM_BYTES);
    cudaFuncSetAttribute(flash_hmma_kernel,
                         cudaFuncAttributeMaxDynamicSharedMemorySize, FA_SMEM_BYTES);

    // 0) rotary table + operand conversion
    rottab_kernel<<<(S_LEN * 64) / 256, 256>>>(rottab);
    cvt_f32_f16<<<(M_ROWS * HID) / 1024, 256>>>(hidden, h16);
    split_f32_f16x2<<<(QKV_N * HID) / 1024, 256>>>(w_qkv, wqh16, wql16);
    split_f32_f16x2<<<(HID * HID) / 1024, 256>>>(w_dense, wdh16, wdl16);

    // 1) QKV projection (fp16x2) with fused rotary + bf16 hi/lo split epilogue
    f16x2_gemm_nt<1><<<dim3(QKV_N / TBN, M_ROWS / TBM), 256, GEMM_SMEM_BYTES>>>(
        h16, wqh16, wql16, b_qkv, nullptr, rottab,
        qh, ql, kh, kl, vh, vl, M_ROWS, QKV_N, HID);

    // 2) Causal flash attention (bf16x3) -> ctx fp16
    flash_hmma_kernel<<<dim3(S_LEN / FBM, NP, BATCH), 256, FA_SMEM_BYTES>>>(
        qh, ql, kh, kl, vh, vl, c16);

    // 3) Dense projection (fp16x2, plain epilogue)
    f16x2_gemm_nt<0><<<dim3(HID / TBN, M_ROWS / TBM), 256, GEMM_SMEM_BYTES>>>(
        c16, wdh16, wdl16, b_dense, out, nullptr,
        nullptr, nullptr, nullptr, nullptr, nullptr, nullptr, M_ROWS, HID, HID);
}

// round 16
// speedup vs baseline: 1.7956x; 1.0910x over previous
#include <cuda_runtime.h>
#include <cuda_bf16.h>
#include <cuda_fp16.h>
#include <math.h>
#include <stdint.h>

// Problem constants
#define S_LEN 2048
#define BATCH 2
#define HID   2048
#define NP    16
#define HN    128
#define M_ROWS (S_LEN*BATCH)     // 4096
#define QKV_N  (3*HID)           // 6144
#define HEAD_ELEMS ((size_t)BATCH * NP * S_LEN * HN)   // 8388608

// ---------------------------------------------------------------------------
// Scratch (device globals; no runtime allocation allowed)
// ---------------------------------------------------------------------------
__device__ __nv_bfloat16 g_qh[HEAD_ELEMS], g_ql[HEAD_ELEMS];    // [b][n][s][d]
__device__ __nv_bfloat16 g_kh[HEAD_ELEMS], g_kl[HEAD_ELEMS];
__device__ __nv_bfloat16 g_vh[HEAD_ELEMS], g_vl[HEAD_ELEMS];
__device__ __half g_h16[(size_t)M_ROWS * HID];                  // hidden fp16
__device__ __half g_wqh16[(size_t)QKV_N * HID], g_wql16[(size_t)QKV_N * HID];
__device__ __half g_wdh16[(size_t)HID * HID];
__device__ __half g_c16[(size_t)M_ROWS * HID];                  // ctx fp16
__device__ float2 g_rottab[S_LEN * 64];                         // (cos,sin)[s][i]

// ---------------------------------------------------------------------------
// PTX helpers
// ---------------------------------------------------------------------------
__device__ __forceinline__ uint32_t smem_u32(const void* p) {
    return (uint32_t)__cvta_generic_to_shared(p);
}
__device__ __forceinline__ void ldsm_x4(uint32_t& r0, uint32_t& r1,
                                        uint32_t& r2, uint32_t& r3, uint32_t addr) {
    asm volatile("ldmatrix.sync.aligned.m8n8.x4.shared.b16 {%0,%1,%2,%3}, [%4];"
        : "=r"(r0), "=r"(r1), "=r"(r2), "=r"(r3) : "r"(addr));
}
__device__ __forceinline__ void ldsm_x4_t(uint32_t& r0, uint32_t& r1,
                                          uint32_t& r2, uint32_t& r3, uint32_t addr) {
    asm volatile("ldmatrix.sync.aligned.m8n8.x4.trans.shared.b16 {%0,%1,%2,%3}, [%4];"
        : "=r"(r0), "=r"(r1), "=r"(r2), "=r"(r3) : "r"(addr));
}
__device__ __forceinline__ void mma_bf16(float* d, const uint32_t* a, const uint32_t* b) {
    asm volatile("mma.sync.aligned.m16n8k16.row.col.f32.bf16.bf16.f32 "
        "{%0,%1,%2,%3}, {%4,%5,%6,%7}, {%8,%9}, {%0,%1,%2,%3};"
        : "+f"(d[0]), "+f"(d[1]), "+f"(d[2]), "+f"(d[3])
        : "r"(a[0]), "r"(a[1]), "r"(a[2]), "r"(a[3]), "r"(b[0]), "r"(b[1]));
}
__device__ __forceinline__ void mma_f16(float* d, const uint32_t* a, const uint32_t* b) {
    asm volatile("mma.sync.aligned.m16n8k16.row.col.f32.f16.f16.f32 "
        "{%0,%1,%2,%3}, {%4,%5,%6,%7}, {%8,%9}, {%0,%1,%2,%3};"
        : "+f"(d[0]), "+f"(d[1]), "+f"(d[2]), "+f"(d[3])
        : "r"(a[0]), "r"(a[1]), "r"(a[2]), "r"(a[3]), "r"(b[0]), "r"(b[1]));
}
__device__ __forceinline__ uint32_t pack_bf2(float a, float b) {
    __nv_bfloat162 t;
    t.x = __float2bfloat16_rn(a);
    t.y = __float2bfloat16_rn(b);
    return *(uint32_t*)&t;
}
__device__ __forceinline__ void cp16(void* sdst, const void* gsrc) {
    asm volatile("cp.async.cg.shared.global [%0], [%1], 16;\n"
        :: "r"(smem_u32(sdst)), "l"(gsrc));
}
__device__ __forceinline__ void cp_commit() {
    asm volatile("cp.async.commit_group;\n");
}
template <int N>
__device__ __forceinline__ void cp_wait() {
    asm volatile("cp.async.wait_group %0;\n" :: "n"(N));
}
__device__ __forceinline__ void split_store(__nv_bfloat16* H, __nv_bfloat16* L,
                                            size_t idx, float v) {
    __nv_bfloat16 h = __float2bfloat16_rn(v);
    H[idx] = h;
    L[idx] = __float2bfloat16_rn(v - __bfloat162float(h));
}

// ---------------------------------------------------------------------------
// rotary (cos,sin) table: [s][i], i in [0,64)
// ---------------------------------------------------------------------------
__global__ __launch_bounds__(256) void rottab_kernel(float2* __restrict__ tab) {
    int idx = blockIdx.x * 256 + threadIdx.x;      // 131072 total
    int s = idx >> 6, i = idx & 63;
    float expo = (float)(2 * i) / (float)HN;
    float freq = powf(1e-4f, expo);
    float ang  = (float)s * freq;
    float sn, cs;
    sincosf(ang, &sn, &cs);
    tab[idx] = make_float2(cs, sn);
}

// ---------------------------------------------------------------------------
// fp32 -> fp16 hi only
// ---------------------------------------------------------------------------
__global__ __launch_bounds__(256) void cvt_f32_f16(
    const float* __restrict__ src, __half* __restrict__ dst)
{
    size_t i = ((size_t)blockIdx.x * 256 + threadIdx.x) * 4;
    float4 v = *(const float4*)(src + i);
    __half2 t;
    t.x = __float2half_rn(v.x); t.y = __float2half_rn(v.y);
    *(__half2*)(dst + i) = t;
    t.x = __float2half_rn(v.z); t.y = __float2half_rn(v.w);
    *(__half2*)(dst + i + 2) = t;
}

// ---------------------------------------------------------------------------
// fp32 -> fp16 hi/lo split (QKV weights)
// ---------------------------------------------------------------------------
__global__ __launch_bounds__(256) void split_f32_f16x2(
    const float* __restrict__ src,
    __half* __restrict__ hi, __half* __restrict__ lo)
{
    size_t i = ((size_t)blockIdx.x * 256 + threadIdx.x) * 4;
    float4 v = *(const float4*)(src + i);
    __half h0 = __float2half_rn(v.x);
    __half h1 = __float2half_rn(v.y);
    __half h2 = __float2half_rn(v.z);
    __half h3 = __float2half_rn(v.w);
    __half2 t;
    t.x = h0; t.y = h1; *(__half2*)(hi + i)     = t;
    t.x = h2; t.y = h3; *(__half2*)(hi + i + 2) = t;
    t.x = __float2half_rn(v.x - __half2float(h0));
    t.y = __float2half_rn(v.y - __half2float(h1));
    *(__half2*)(lo + i) = t;
    t.x = __float2half_rn(v.z - __half2float(h2));
    t.y = __float2half_rn(v.w - __half2float(h3));
    *(__half2*)(lo + i + 2) = t;
}

// ---------------------------------------------------------------------------
// fp16 GEMM (NT): C = A16 * B^T + bias
// NPROD=2: B = Bh + Bl (2 mma products). NPROD=1: B = Bh only.
// 4-stage cp.async pipeline (distance 3), ONE sync per k-tile, packed
// XOR-swizzled smem, 2 CTAs/SM. BM=BN=128, BK=32, 256 thr, warp tile 32x64.
// FUSE=1: QKV epilogue (rotary + bf16 hi/lo split to [b][n][s][d] planes).
// ---------------------------------------------------------------------------
#define TBM 128
#define TBN 128
#define TBK 32
#define NSTAGE 4
#define PLANE_E (128*32)                     // 4096 halves per plane
#define STAGE_E (3*PLANE_E)                  // A|Bh|Bl slots = 24 KB
#define GEMM_SMEM_BYTES (NSTAGE*STAGE_E*2)   // 98304 B (x2 CTAs = 192 KB/SM)
#define EPI_STR 136                          // fp32 epilogue smem stride

__device__ __forceinline__ int swz_off(int row, int chunk) {
    return row * 32 + ((chunk ^ ((row >> 1) & 3)) << 3);
}

template <int FUSE, int NPROD>
__global__ __launch_bounds__(256, 2) void f16_gemm_nt(
    const __half* __restrict__ A16,
    const __half* __restrict__ Bh, const __half* __restrict__ Bl,
    const float* __restrict__ bias, float* __restrict__ C,
    const float2* __restrict__ rottab,
    __nv_bfloat16* __restrict__ Qh, __nv_bfloat16* __restrict__ Ql,
    __nv_bfloat16* __restrict__ Kh, __nv_bfloat16* __restrict__ Kl,
    __nv_bfloat16* __restrict__ Vh, __nv_bfloat16* __restrict__ Vl,
    int M, int N, int K)
{
    extern __shared__ __half smg[];

    const int tid  = threadIdx.x;
    const int bx   = blockIdx.x, by = blockIdx.y;
    const int warp = tid >> 5, lane = tid & 31;
    const int wr   = warp & 3;
    const int wc   = warp >> 2;

    auto prefetch = [&](int kt, int s) {
        __half* st = smg + (size_t)s * STAGE_E;
        const size_t kof = (size_t)kt * TBK;
#pragma unroll
        for (int j = 0; j < 2; j++) {
            int lin = tid + j * 256;          // 512 chunks per plane
            int r = lin >> 2, c = lin & 3;
            int so = swz_off(r, c);
            size_t ga = (size_t)(by * TBM + r) * K + kof + c * 8;
            size_t gb = (size_t)(bx * TBN + r) * K + kof + c * 8;
            cp16(st + so,           A16 + ga);
            cp16(st + PLANE_E + so, Bh + gb);
            if (NPROD == 2) cp16(st + 2 * PLANE_E + so, Bl + gb);
        }
    };

    float acc[2][8][4];
#pragma unroll
    for (int mi = 0; mi < 2; mi++)
#pragma unroll
        for (int ni = 0; ni < 8; ni++)
#pragma unroll
            for (int e = 0; e < 4; e++) acc[mi][ni][e] = 0.f;

    const int a_row = wr * 32 + (lane & 15);
    const int a_kc  = lane >> 4;
    const int bg    = lane >> 3;
    const int b_row = wc * 64 + ((bg >> 1) << 3) + (lane & 7);
    const int b_kc  = bg & 1;

    auto compute = [&](int s) {
        const __half* A0 = smg + (size_t)s * STAGE_E;
        const __half* B0 = A0 + PLANE_E;
        const __half* B1 = A0 + 2 * PLANE_E;
#pragma unroll
        for (int kk = 0; kk < 2; kk++) {
            uint32_t af[2][4];
#pragma unroll
            for (int mi = 0; mi < 2; mi++) {
                int ra = a_row + mi * 16;
                int off = swz_off(ra, kk * 2 + a_kc);
                ldsm_x4(af[mi][0], af[mi][1], af[mi][2], af[mi][3],
                        smem_u32(A0 + off));
            }
#pragma unroll
            for (int np = 0; np < 4; np++) {
                int rb = b_row + np * 16;
                int off = swz_off(rb, kk * 2 + b_kc);
                uint32_t b0[4], b1[4];
                ldsm_x4(b0[0], b0[1], b0[2], b0[3], smem_u32(B0 + off));
                if (NPROD == 2)
                    ldsm_x4(b1[0], b1[1], b1[2], b1[3], smem_u32(B1 + off));
#pragma unroll
                for (int mi = 0; mi < 2; mi++) {
                    mma_f16(acc[mi][np * 2],     af[mi], b0);
                    if (NPROD == 2) mma_f16(acc[mi][np * 2], af[mi], b1);
                    mma_f16(acc[mi][np * 2 + 1], af[mi], b0 + 2);
                    if (NPROD == 2) mma_f16(acc[mi][np * 2 + 1], af[mi], b1 + 2);
                }
            }
        }
    };

    const int nt = K / TBK;
    prefetch(0, 0); cp_commit();
    prefetch(1, 1); cp_commit();
    prefetch(2, 2); cp_commit();
#pragma unroll 1
    for (int kt = 0; kt < nt; kt++) {
        cp_wait<2>();
        __syncthreads();                 // stage kt%4 resident; stage (kt-1)%4 drained
        if (kt + 3 < nt) prefetch(kt + 3, (kt + 3) % NSTAGE);
        cp_commit();
        compute(kt % NSTAGE);
    }

    const int gr = lane >> 2, gc = (lane & 3) * 2;

    if (FUSE == 0) {
        // ---- plain epilogue: bias + fp32 C ----
#pragma unroll
        for (int mi = 0; mi < 2; mi++) {
            int row = by * TBM + wr * 32 + mi * 16 + gr;
#pragma unroll
            for (int ni = 0; ni < 8; ni++) {
                int col = bx * TBN + wc * 64 + ni * 8 + gc;
                float b0 = bias[col], b1 = bias[col + 1];
                float2 v0, v1;
                v0.x = acc[mi][ni][0] + b0; v0.y = acc[mi][ni][1] + b1;
                v1.x = acc[mi][ni][2] + b0; v1.y = acc[mi][ni][3] + b1;
                *(float2*)&C[(size_t)row * N + col] = v0;
                *(float2*)&C[(size_t)(row + 8) * N + col] = v1;
            }
        }
    } else {
        // ---- fused QKV epilogue: stage tile (+bias) in smem fp32 ----
        __syncthreads();    // all compute + smem reads done; reuse smem
        float* sc = (float*)smg;            // [128][EPI_STR] = 69632 B
#pragma unroll
        for (int mi = 0; mi < 2; mi++) {
            int row = wr * 32 + mi * 16 + gr;
#pragma unroll
            for (int ni = 0; ni < 8; ni++) {
                int col = wc * 64 + ni * 8 + gc;
                int gcol = bx * TBN + col;
                float b0 = bias[gcol], b1 = bias[gcol + 1];
                sc[row * EPI_STR + col]           = acc[mi][ni][0] + b0;
                sc[row * EPI_STR + col + 1]       = acc[mi][ni][1] + b1;
                sc[(row + 8) * EPI_STR + col]     = acc[mi][ni][2] + b0;
                sc[(row + 8) * EPI_STR + col + 1] = acc[mi][ni][3] + b1;
            }
        }
        __syncthreads();

        const int type = bx % 3;            // 0=q, 1=k, 2=v
        const int n    = bx / 3;
        const float qscale = 0.0883883476483184f;   // 1/sqrt(128)

        if (type < 2) {
            __nv_bfloat16* H = (type == 0) ? Qh : Kh;
            __nv_bfloat16* L = (type == 0) ? Ql : Kl;
#pragma unroll 4
            for (int j = 0; j < 32; j++) {
                int p = tid + j * 256;      // 0..8191
                int r = p >> 6;
                int i = p & 63;
                int grow = by * TBM + r;    // s*BATCH + b
                int s = grow >> 1, bb = grow & 1;
                float Lv = sc[r * EPI_STR + i];
                float Rv = sc[r * EPI_STR + i + 64];
                float2 cssn = rottab[s * 64 + i];
                float x0 = cssn.x * Lv - cssn.y * Rv;
                float x1 = cssn.y * Lv + cssn.x * Rv;
                if (type == 0) { x0 *= qscale; x1 *= qscale; }
                size_t dst = (((size_t)bb * NP + n) * S_LEN + s) * HN;
                split_store(H, L, dst + i,      x0);
                split_store(H, L, dst + i + 64, x1);
            }
        } else {
#pragma unroll 4
            for (int j = 0; j < 64; j++) {
                int p = tid + j * 256;      // 0..16383
                int r = p >> 7;
                int c = p & 127;
                int grow = by * TBM + r;
                int s = grow >> 1, bb = grow & 1;
                float x = sc[r * EPI_STR + c];
                size_t dst = (((size_t)bb * NP + n) * S_LEN + s) * HN + c;
                split_store(Vh, Vl, dst, x);
            }
        }
    }
}

// ---------------------------------------------------------------------------
// HMMA flash attention (bf16x3), cp.async double-buffered; ctx out fp16.
// (unchanged from R15 passing version)
// ---------------------------------------------------------------------------
#define FBM 128
#define FBN 64
#define FSTR 136
#define FA_STAGE_ELEMS (4*FBN*FSTR)
#define FA_SMEM_BYTES ((2*FBM*FSTR + 2*FA_STAGE_ELEMS) * 2)   // 208896

__global__ __launch_bounds__(256, 1) void flash_hmma_kernel(
    const __nv_bfloat16* __restrict__ Qhg, const __nv_bfloat16* __restrict__ Qlg,
    const __nv_bfloat16* __restrict__ Khg, const __nv_bfloat16* __restrict__ Klg,
    const __nv_bfloat16* __restrict__ Vhg, const __nv_bfloat16* __restrict__ Vlg,
    __half* __restrict__ C16)
{
    extern __shared__ __nv_bfloat16 fsm[];
    __nv_bfloat16* Qh = fsm;
    __nv_bfloat16* Ql = Qh + FBM * FSTR;
    __nv_bfloat16* St = Ql + FBM * FSTR;

    const int qt = gridDim.x - 1 - blockIdx.x;
    const int n  = blockIdx.y;
    const int b  = blockIdx.z;
    const int tid  = threadIdx.x;
    const int warp = tid >> 5, lane = tid & 31;

    const size_t head = ((size_t)b * NP + n) * (size_t)S_LEN * HN;
    const int row0 = qt * FBM;

    auto prefetch = [&](int kt, int s) {
        __nv_bfloat16* Khs = St + (size_t)s * FA_STAGE_ELEMS;
        __nv_bfloat16* Kls = Khs + FBN * FSTR;
        __nv_bfloat16* Vhs = Kls + FBN * FSTR;
        __nv_bfloat16* Vls = Vhs + FBN * FSTR;
        size_t base = head + (size_t)(kt * FBN) * HN;
#pragma unroll
        for (int j = 0; j < 4; j++) {
            int lin = tid + j * 256;
            int r = lin >> 4, c = (lin & 15) * 8;
            size_t g = base + (size_t)r * HN + c;
            int so = r * FSTR + c;
            cp16(&Khs[so], Khg + g);
            cp16(&Kls[so], Klg + g);
            cp16(&Vhs[so], Vhg + g);
            cp16(&Vls[so], Vlg + g);
        }
    };

#pragma unroll
    for (int j = 0; j < 8; j++) {
        int lin = tid + j * 256;
        int r = lin >> 4, c = (lin & 15) * 8;
        size_t g = head + (size_t)(row0 + r) * HN + c;
        cp16(&Qh[r * FSTR + c], Qhg + g);
        cp16(&Ql[r * FSTR + c], Qlg + g);
    }
    prefetch(0, 0);
    cp_commit();

    float oacc[16][4];
#pragma unroll
    for (int t = 0; t < 16; t++)
#pragma unroll
        for (int e = 0; e < 4; e++) oacc[t][e] = 0.f;
    float m_i[2] = {-1e30f, -1e30f};
    float l_i[2] = {0.f, 0.f};

    const int a_row = warp * 16 + (lane & 15);
    const int a_kh  = (lane >> 4) * 8;
    const int b_r   = (lane >> 4) * 8 + (lane & 7);
    const int b_kh  = ((lane >> 3) & 1) * 8;
    const int v_row = ((lane >> 3) & 1) * 8 + (lane & 7);
    const int v_col = (lane >> 4) * 8;
    const int gr    = lane >> 2;
    const int gc    = (lane & 3) * 2;
    const int wrow_last = row0 + warp * 16 + 15;

    const int nkt = (row0 + FBM) / FBN;
#pragma unroll 1
    for (int kt = 0; kt < nkt; kt++) {
        const int kr0 = kt * FBN;
        const int s = kt & 1;

        if (kt + 1 < nkt) {
            prefetch(kt + 1, (kt + 1) & 1);
            cp_commit();
            cp_wait<1>();
        } else {
            cp_wait<0>();
        }
        __syncthreads();

        if (kr0 <= wrow_last) {
            __nv_bfloat16* Khs = St + (size_t)s * FA_STAGE_ELEMS;
            __nv_bfloat16* Kls = Khs + FBN * FSTR;
            __nv_bfloat16* Vhs = Kls + FBN * FSTR;
            __nv_bfloat16* Vls = Vhs + FBN * FSTR;

            float sacc[8][4];
#pragma unroll
            for (int t = 0; t < 8; t++)
#pragma unroll
                for (int e = 0; e < 4; e++) sacc[t][e] = 0.f;

#pragma unroll
            for (int kk = 0; kk < 8; kk++) {
                uint32_t aH[4], aL[4];
                ldsm_x4(aH[0], aH[1], aH[2], aH[3],
                        smem_u32(&Qh[a_row * FSTR + kk * 16 + a_kh]));
                ldsm_x4(aL[0], aL[1], aL[2], aL[3],
                        smem_u32(&Ql[a_row * FSTR + kk * 16 + a_kh]));
#pragma unroll
                for (int nt2 = 0; nt2 < 4; nt2++) {
                    uint32_t bh[4], bl[4];
                    ldsm_x4(bh[0], bh[1], bh[2], bh[3],
                            smem_u32(&Khs[(nt2 * 16 + b_r) * FSTR + kk * 16 + b_kh]));
                    ldsm_x4(bl[0], bl[1], bl[2], bl[3],
                            smem_u32(&Kls[(nt2 * 16 + b_r) * FSTR + kk * 16 + b_kh]));
                    mma_bf16(sacc[nt2 * 2], aH, bh);
                    mma_bf16(sacc[nt2 * 2], aH, bl);
                    mma_bf16(sacc[nt2 * 2], aL, bh);
                    mma_bf16(sacc[nt2 * 2 + 1], aH, bh + 2);
                    mma_bf16(sacc[nt2 * 2 + 1], aH, bl + 2);
                    mma_bf16(sacc[nt2 * 2 + 1], aL, bh + 2);
                }
            }

            if (kr0 + FBN - 1 > row0 + warp * 16) {
                int grow0 = row0 + warp * 16 + gr;
#pragma unroll
                for (int t = 0; t < 8; t++) {
                    int colb = kr0 + t * 8 + gc;
                    if (colb     > grow0)     sacc[t][0] = -1e30f;
                    if (colb + 1 > grow0)     sacc[t][1] = -1e30f;
                    if (colb     > grow0 + 8) sacc[t][2] = -1e30f;
                    if (colb + 1 > grow0 + 8) sacc[t][3] = -1e30f;
                }
            }

            float mx0 = -1e30f, mx1 = -1e30f;
#pragma unroll
            for (int t = 0; t < 8; t++) {
                mx0 = fmaxf(mx0, fmaxf(sacc[t][0], sacc[t][1]));
                mx1 = fmaxf(mx1, fmaxf(sacc[t][2], sacc[t][3]));
            }
            mx0 = fmaxf(mx0, __shfl_xor_sync(0xffffffffu, mx0, 1));
            mx0 = fmaxf(mx0, __shfl_xor_sync(0xffffffffu, mx0, 2));
            mx1 = fmaxf(mx1, __shfl_xor_sync(0xffffffffu, mx1, 1));
            mx1 = fmaxf(mx1, __shfl_xor_sync(0xffffffffu, mx1, 2));
            float mn0 = fmaxf(m_i[0], mx0);
            float mn1 = fmaxf(m_i[1], mx1);
            float corr0 = __expf(m_i[0] - mn0);
            float corr1 = __expf(m_i[1] - mn1);

            uint32_t aPh[4][4], aPl[4][4];
            float rs0 = 0.f, rs1 = 0.f;
#pragma unroll
            for (int t = 0; t < 8; t++) {
                float p00 = __expf(sacc[t][0] - mn0);
                float p01 = __expf(sacc[t][1] - mn0);
                float p10 = __expf(sacc[t][2] - mn1);
                float p11 = __expf(sacc[t][3] - mn1);
                rs0 += p00 + p01;
                rs1 += p10 + p11;
                int kc = t >> 1, half = (t & 1) * 2;
                float h00 = __bfloat162float(__float2bfloat16_rn(p00));
                float h01 = __bfloat162float(__float2bfloat16_rn(p01));
                float h10 = __bfloat162float(__float2bfloat16_rn(p10));
                float h11 = __bfloat162float(__float2bfloat16_rn(p11));
                aPh[kc][half]     = pack_bf2(h00, h01);
                aPh[kc][half + 1] = pack_bf2(h10, h11);
                aPl[kc][half]     = pack_bf2(p00 - h00, p01 - h01);
                aPl[kc][half + 1] = pack_bf2(p10 - h10, p11 - h11);
            }
            rs0 += __shfl_xor_sync(0xffffffffu, rs0, 1);
            rs0 += __shfl_xor_sync(0xffffffffu, rs0, 2);
            rs1 += __shfl_xor_sync(0xffffffffu, rs1, 1);
            rs1 += __shfl_xor_sync(0xffffffffu, rs1, 2);
            l_i[0] = l_i[0] * corr0 + rs0;  m_i[0] = mn0;
            l_i[1] = l_i[1] * corr1 + rs1;  m_i[1] = mn1;

#pragma unroll
            for (int t = 0; t < 16; t++) {
                oacc[t][0] *= corr0; oacc[t][1] *= corr0;
                oacc[t][2] *= corr1; oacc[t][3] *= corr1;
            }

#pragma unroll
            for (int kc = 0; kc < 4; kc++) {
#pragma unroll
                for (int nt2 = 0; nt2 < 8; nt2++) {
                    uint32_t bh[4], bl[4];
                    ldsm_x4_t(bh[0], bh[1], bh[2], bh[3],
                              smem_u32(&Vhs[(kc * 16 + v_row) * FSTR + nt2 * 16 + v_col]));
                    ldsm_x4_t(bl[0], bl[1], bl[2], bl[3],
                              smem_u32(&Vls[(kc * 16 + v_row) * FSTR + nt2 * 16 + v_col]));
                    mma_bf16(oacc[nt2 * 2], aPh[kc], bh);
                    mma_bf16(oacc[nt2 * 2], aPh[kc], bl);
                    mma_bf16(oacc[nt2 * 2], aPl[kc], bh);
                    mma_bf16(oacc[nt2 * 2 + 1], aPh[kc], bh + 2);
                    mma_bf16(oacc[nt2 * 2 + 1], aPh[kc], bl + 2);
                    mma_bf16(oacc[nt2 * 2 + 1], aPl[kc], bh + 2);
                }
            }
        }

        __syncthreads();
    }

    {
        float inv0 = 1.0f / l_i[0];
        float inv1 = 1.0f / l_i[1];
        int s0 = row0 + warp * 16 + gr;
        size_t o0 = ((size_t)s0 * BATCH + b) * HID + n * HN;
        size_t o1 = ((size_t)(s0 + 8) * BATCH + b) * HID + n * HN;
#pragma unroll
        for (int t = 0; t < 16; t++) {
            int col = t * 8 + gc;
            __half2 t2;
            t2.x = __float2half_rn(oacc[t][0] * inv0);
            t2.y = __float2half_rn(oacc[t][1] * inv0);
            *(__half2*)&C16[o0 + col] = t2;
            t2.x = __float2half_rn(oacc[t][2] * inv1);
            t2.y = __float2half_rn(oacc[t][3] * inv1);
            *(__half2*)&C16[o1 + col] = t2;
        }
    }
}

// ---------------------------------------------------------------------------
// Launch
// ---------------------------------------------------------------------------
extern "C" void kernel_launch(void* const* d_in, const int* in_sizes, int n_in,
                              void* d_out, int out_size)
{
    const float* hidden  = (const float*)d_in[0];
    // d_in[1] = attention_mask (causal; handled analytically)
    const float* w_qkv   = (const float*)d_in[2];
    const float* b_qkv   = (const float*)d_in[3];
    const float* w_dense = (const float*)d_in[4];
    const float* b_dense = (const float*)d_in[5];
    float* out = (float*)d_out;

    __nv_bfloat16 *qh, *ql, *kh, *kl, *vh, *vl;
    __half *h16, *wqh16, *wql16, *wdh16, *c16;
    float2* rottab;
    cudaGetSymbolAddress((void**)&qh,  g_qh);
    cudaGetSymbolAddress((void**)&ql,  g_ql);
    cudaGetSymbolAddress((void**)&kh,  g_kh);
    cudaGetSymbolAddress((void**)&kl,  g_kl);
    cudaGetSymbolAddress((void**)&vh,  g_vh);
    cudaGetSymbolAddress((void**)&vl,  g_vl);
    cudaGetSymbolAddress((void**)&h16,   g_h16);
    cudaGetSymbolAddress((void**)&wqh16, g_wqh16);
    cudaGetSymbolAddress((void**)&wql16, g_wql16);
    cudaGetSymbolAddress((void**)&wdh16, g_wdh16);
    cudaGetSymbolAddress((void**)&c16,   g_c16);
    cudaGetSymbolAddress((void**)&rottab, g_rottab);

    cudaFuncSetAttribute((const void*)f16_gemm_nt<0, 1>,
                         cudaFuncAttributeMaxDynamicSharedMemorySize, GEMM_SMEM_BYTES);
    cudaFuncSetAttribute((const void*)f16_gemm_nt<1, 2>,
                         cudaFuncAttributeMaxDynamicSharedMemorySize, GEMM_SMEM_BYTES);
    cudaFuncSetAttribute(flash_hmma_kernel,
                         cudaFuncAttributeMaxDynamicSharedMemorySize, FA_SMEM_BYTES);

    // 0) rotary table + operand conversion
    rottab_kernel<<<(S_LEN * 64) / 256, 256>>>(rottab);
    cvt_f32_f16<<<(M_ROWS * HID) / 1024, 256>>>(hidden, h16);
    split_f32_f16x2<<<(QKV_N * HID) / 1024, 256>>>(w_qkv, wqh16, wql16);
    cvt_f32_f16<<<(HID * HID) / 1024, 256>>>(w_dense, wdh16);

    // 1) QKV projection (fp16 x2 products) with fused rotary + split epilogue
    f16_gemm_nt<1, 2><<<dim3(QKV_N / TBN, M_ROWS / TBM), 256, GEMM_SMEM_BYTES>>>(
        h16, wqh16, wql16, b_qkv, nullptr, rottab,
        qh, ql, kh, kl, vh, vl, M_ROWS, QKV_N, HID);

    // 2) Causal flash attention (bf16x3) -> ctx fp16
    flash_hmma_kernel<<<dim3(S_LEN / FBM, NP, BATCH), 256, FA_SMEM_BYTES>>>(
        qh, ql, kh, kl, vh, vl, c16);

    // 3) Dense projection (fp16 x1 product, plain epilogue)
    f16_gemm_nt<0, 1><<<dim3(HID / TBN, M_ROWS / TBM), 256, GEMM_SMEM_BYTES>>>(
        c16, wdh16, nullptr, b_dense, out, nullptr,
        nullptr, nullptr, nullptr, nullptr, nullptr, nullptr, M_ROWS, HID, HID);
}